// round 10
// baseline (speedup 1.0000x reference)
#include <cuda_runtime.h>
#include <cuda_bf16.h>
#include <math.h>
#include <stdint.h>

// ---------------------------------------------------------------------------
// Problem constants
// ---------------------------------------------------------------------------
#define BB    32
#define HH    112
#define WW2   112
#define CC    96
#define NHH   3
#define WSS   7
#define SHF   3
#define HIDD  384
#define NTOK  49
#define HDD   32
#define NWIN  8192
#define MTOK  401408

typedef __nv_bfloat16 bf16;
typedef __nv_bfloat162 bf162;

// ---------------------------------------------------------------------------
// Scratch (device globals)
// ---------------------------------------------------------------------------
__device__ __align__(16) bf16  g_qh[(size_t)NWIN * NHH * NTOK * HDD];
__device__ __align__(16) bf16  g_kh[(size_t)NWIN * NHH * NTOK * HDD];
__device__ __align__(16) bf16  g_vh[(size_t)NWIN * NHH * NTOK * HDD];
__device__ __align__(16) bf16  g_atth[(size_t)MTOK * CC];
__device__ __align__(16) float g_x1[(size_t)MTOK * CC];
__device__ __align__(16) float g_comb[(size_t)256 * NHH * NTOK * NTOK];
__device__ __align__(16) bf16 g_wqkv[288 * 96];
__device__ __align__(16) bf16 g_wproj[96 * 96];
__device__ __align__(16) bf16 g_wfc1[384 * 96];
__device__ __align__(16) bf16 g_wfc2[96 * 384];

__device__ __forceinline__ int rowsrc(int m) {
    int win = m / NTOK, tok = m - win * NTOK;
    int b = win >> 8, widx = win & 255;
    int wh = widx >> 4, ww = widx & 15;
    int r = tok / WSS, c = tok - r * WSS;
    int h = wh * WSS + r + SHF; if (h >= HH) h -= HH;
    int w = ww * WSS + c + SHF; if (w >= WW2) w -= WW2;
    return (b * HH + h) * WW2 + w;
}

// ---------------------------------------------------------------------------
// Weight conversion
// ---------------------------------------------------------------------------
__global__ void __launch_bounds__(256) k_prep(const float* __restrict__ qkvw,
                                              const float* __restrict__ projw,
                                              const float* __restrict__ fc1w,
                                              const float* __restrict__ fc2w) {
    int i = blockIdx.x * 256 + threadIdx.x;
    if (i < 27648)               g_wqkv[i]           = __float2bfloat16(qkvw[i]);
    else if (i < 27648 + 9216)   g_wproj[i - 27648]  = __float2bfloat16(projw[i - 27648]);
    else if (i < 36864 + 36864)  g_wfc1[i - 36864]   = __float2bfloat16(fc1w[i - 36864]);
    else if (i < 110592)         g_wfc2[i - 73728]   = __float2bfloat16(fc2w[i - 73728]);
}

// ---------------------------------------------------------------------------
// Combined additive bias
// ---------------------------------------------------------------------------
__global__ void __launch_bounds__(256) k_comb(const float* __restrict__ mask,
                                              const int* __restrict__ ridx,
                                              const float* __restrict__ table) {
    int wh = blockIdx.x;
    int widx = wh / 3, head = wh - widx * 3;
    const int NN = NTOK * NTOK;
    float* dst = g_comb + (size_t)wh * NN;
    const float* msk = mask + (size_t)widx * NN;
    for (int idx = threadIdx.x; idx < NN; idx += 256)
        dst[idx] = msk[idx] + table[ridx[idx] * NHH + head];
}

// ---------------------------------------------------------------------------
// BF16 mma helper
// ---------------------------------------------------------------------------
__device__ __forceinline__ void mma_bf16(float* c, const uint32_t* a, const uint32_t* b) {
    asm volatile(
        "mma.sync.aligned.m16n8k16.row.col.f32.bf16.bf16.f32 "
        "{%0,%1,%2,%3}, {%4,%5,%6,%7}, {%8,%9}, {%0,%1,%2,%3};"
        : "+f"(c[0]), "+f"(c[1]), "+f"(c[2]), "+f"(c[3])
        : "r"(a[0]), "r"(a[1]), "r"(a[2]), "r"(a[3]), "r"(b[0]), "r"(b[1]));
}

// ---------------------------------------------------------------------------
// Fused LN1 + QKV GEMM.  64 rows/block, 256 threads, 3 n-chunks of 96.
// smem: As 13.3KB + Bs 20KB = 33.3KB
// ---------------------------------------------------------------------------
__global__ void __launch_bounds__(256) k_qkv(const float* __restrict__ x,
                                             const float* __restrict__ g,
                                             const float* __restrict__ b,
                                             const float* __restrict__ bias) {
    __shared__ __align__(16) uint32_t As[64][52];
    __shared__ __align__(16) uint32_t Bs[96][52];
    const int tid = threadIdx.x;
    const int wid = tid >> 5, lane = tid & 31;
    const int warp_m = wid >> 2;            // 0..1
    const int warp_n = wid & 3;             // 0..3
    const int grp = lane >> 2, qid = lane & 3;
    const int m0 = blockIdx.x * 64;

    // ---- LayerNorm1 (gathered): warp w rows w*8..w*8+7 ----
    bf16* asb = reinterpret_cast<bf16*>(As);
    for (int r = wid * 8; r < wid * 8 + 8; r++) {
        int src = rowsrc(m0 + r);
        const float* xr = x + (size_t)src * CC;
        float v0 = xr[lane], v1 = xr[lane + 32], v2 = xr[lane + 64];
        float s = v0 + v1 + v2;
#pragma unroll
        for (int o = 16; o > 0; o >>= 1) s += __shfl_xor_sync(0xffffffffu, s, o);
        float mean = s * (1.0f / 96.0f);
        float d0 = v0 - mean, d1 = v1 - mean, d2 = v2 - mean;
        float sq = d0 * d0 + d1 * d1 + d2 * d2;
#pragma unroll
        for (int o = 16; o > 0; o >>= 1) sq += __shfl_xor_sync(0xffffffffu, sq, o);
        float rstd = rsqrtf(sq * (1.0f / 96.0f) + 1e-5f);
        asb[r * 104 + lane]      = (bf16)(d0 * rstd * g[lane]      + b[lane]);
        asb[r * 104 + lane + 32] = (bf16)(d1 * rstd * g[lane + 32] + b[lane + 32]);
        asb[r * 104 + lane + 64] = (bf16)(d2 * rstd * g[lane + 64] + b[lane + 64]);
    }
    __syncthreads();

    for (int nc = 0; nc < 3; nc++) {
        // load weight chunk rows nc*96..+95
        for (int i = tid; i < 1152; i += 256) {
            int row = i / 12, c8 = i - row * 12;
            *reinterpret_cast<uint4*>(&Bs[row][c8 * 4]) =
                *reinterpret_cast<const uint4*>(g_wqkv + (size_t)(nc * 96 + row) * 96 + c8 * 8);
        }
        __syncthreads();

        float c[2][3][4];
#pragma unroll
        for (int i = 0; i < 2; i++)
#pragma unroll
            for (int j = 0; j < 3; j++)
#pragma unroll
                for (int e = 0; e < 4; e++) c[i][j][e] = 0.f;
#pragma unroll
        for (int kk = 0; kk < 48; kk += 8) {
            uint32_t a[2][4], bb[3][2];
#pragma unroll
            for (int i = 0; i < 2; i++) {
                int ar = warp_m * 32 + i * 16 + grp;
                a[i][0] = As[ar][kk + qid];
                a[i][1] = As[ar + 8][kk + qid];
                a[i][2] = As[ar][kk + qid + 4];
                a[i][3] = As[ar + 8][kk + qid + 4];
            }
#pragma unroll
            for (int j = 0; j < 3; j++) {
                int br = warp_n * 24 + j * 8 + grp;
                bb[j][0] = Bs[br][kk + qid];
                bb[j][1] = Bs[br][kk + qid + 4];
            }
#pragma unroll
            for (int i = 0; i < 2; i++)
#pragma unroll
                for (int j = 0; j < 3; j++)
                    mma_bf16(c[i][j], a[i], bb[j]);
        }

        // epilogue: scatter q/k/v (nc selects which)
#pragma unroll
        for (int i = 0; i < 2; i++) {
            int m = m0 + warp_m * 32 + i * 16 + grp;
            int win = m / NTOK, tok = m - win * NTOK;
#pragma unroll
            for (int j = 0; j < 3; j++) {
                int ln = warp_n * 24 + j * 8 + qid * 2;     // 0..94 even
                int n = nc * 96 + ln;
                float a0 = c[i][j][0] + bias[n], a1 = c[i][j][1] + bias[n + 1];
                float a2 = c[i][j][2] + bias[n], a3 = c[i][j][3] + bias[n + 1];
                int head = ln >> 5, d = ln & 31;
                size_t off  = ((size_t)(win * 3 + head) * NTOK + tok) * HDD + d;
                size_t off2 = ((size_t)(win * 3 + head) * NTOK + (tok + 8)) * HDD + d;
                // row m+8 belongs to the same window only if tok+8 < 49; since
                // m0 is a multiple of 64 (not 49) we must recompute:
                int m2 = m + 8;
                int win2 = m2 / NTOK, tok2 = m2 - win2 * NTOK;
                off2 = ((size_t)(win2 * 3 + head) * NTOK + tok2) * HDD + d;
                if (nc == 0) {
                    a0 *= 0.17677669529663689f; a1 *= 0.17677669529663689f;
                    a2 *= 0.17677669529663689f; a3 *= 0.17677669529663689f;
                    *reinterpret_cast<bf162*>(g_qh + off)  = __floats2bfloat162_rn(a0, a1);
                    *reinterpret_cast<bf162*>(g_qh + off2) = __floats2bfloat162_rn(a2, a3);
                } else if (nc == 1) {
                    *reinterpret_cast<bf162*>(g_kh + off)  = __floats2bfloat162_rn(a0, a1);
                    *reinterpret_cast<bf162*>(g_kh + off2) = __floats2bfloat162_rn(a2, a3);
                } else {
                    *reinterpret_cast<bf162*>(g_vh + off)  = __floats2bfloat162_rn(a0, a1);
                    *reinterpret_cast<bf162*>(g_vh + off2) = __floats2bfloat162_rn(a2, a3);
                }
            }
        }
        __syncthreads();    // Bs reads complete before next chunk load
    }
}

// ---------------------------------------------------------------------------
// BF16 tensor-core GEMM (proj): 128x96 tile, BK=96, 8 warps (4m x 2n)
// ---------------------------------------------------------------------------
__global__ void __launch_bounds__(256) k_gemm_proj(const float* __restrict__ pb,
                                                   const float* __restrict__ x) {
    constexpr int ST = 52;
    __shared__ __align__(16) uint32_t As[128][ST];
    __shared__ __align__(16) uint32_t Bs[96][ST];
    const int tid = threadIdx.x;
    const int wid = tid >> 5, lane = tid & 31;
    const int warp_m = wid >> 1, warp_n = wid & 1;
    const int grp = lane >> 2, qid = lane & 3;
    const int m0 = blockIdx.y * 128;

    float c[2][6][4];
#pragma unroll
    for (int i = 0; i < 2; i++)
#pragma unroll
        for (int j = 0; j < 6; j++)
#pragma unroll
            for (int e = 0; e < 4; e++) c[i][j][e] = 0.f;

#pragma unroll
    for (int i = 0; i < 6; i++) {
        int idx = tid + i * 256;
        int row = idx / 12, c8 = idx - row * 12;
        uint4 v = *reinterpret_cast<const uint4*>(g_atth + (size_t)(m0 + row) * 96 + c8 * 8);
        *reinterpret_cast<uint4*>(&As[row][c8 * 4]) = v;
    }
#pragma unroll
    for (int i = 0; i < 5; i++) {
        int idx = tid + i * 256;
        if (idx < 1152) {
            int row = idx / 12, c8 = idx - row * 12;
            uint4 v = *reinterpret_cast<const uint4*>(g_wproj + (size_t)row * 96 + c8 * 8);
            *reinterpret_cast<uint4*>(&Bs[row][c8 * 4]) = v;
        }
    }
    __syncthreads();

#pragma unroll
    for (int kk = 0; kk < 48; kk += 8) {
        uint32_t a[2][4], bv[6][2];
#pragma unroll
        for (int i = 0; i < 2; i++) {
            int ar = warp_m * 32 + i * 16 + grp;
            a[i][0] = As[ar][kk + qid];
            a[i][1] = As[ar + 8][kk + qid];
            a[i][2] = As[ar][kk + qid + 4];
            a[i][3] = As[ar + 8][kk + qid + 4];
        }
#pragma unroll
        for (int j = 0; j < 6; j++) {
            int br = warp_n * 48 + j * 8 + grp;
            bv[j][0] = Bs[br][kk + qid];
            bv[j][1] = Bs[br][kk + qid + 4];
        }
#pragma unroll
        for (int i = 0; i < 2; i++)
#pragma unroll
            for (int j = 0; j < 6; j++)
                mma_bf16(c[i][j], a[i], bv[j]);
    }

#pragma unroll
    for (int i = 0; i < 2; i++) {
        int r0 = m0 + warp_m * 32 + i * 16 + grp;
#pragma unroll
        for (int j = 0; j < 6; j++) {
            int cn = warp_n * 48 + j * 8 + qid * 2;
            {
                int src = rowsrc(r0);
                size_t o = (size_t)src * CC + cn;
                float2 xv = *reinterpret_cast<const float2*>(x + o);
                *reinterpret_cast<float2*>(g_x1 + o) =
                    make_float2(xv.x + c[i][j][0] + pb[cn], xv.y + c[i][j][1] + pb[cn + 1]);
            }
            {
                int src = rowsrc(r0 + 8);
                size_t o = (size_t)src * CC + cn;
                float2 xv = *reinterpret_cast<const float2*>(x + o);
                *reinterpret_cast<float2*>(g_x1 + o) =
                    make_float2(xv.x + c[i][j][2] + pb[cn], xv.y + c[i][j][3] + pb[cn + 1]);
            }
        }
    }
}

// ---------------------------------------------------------------------------
// Fused MLP: LN2 + fc1 + GELU + fc2 + residual.  64 rows/block, 256 threads.
// ---------------------------------------------------------------------------
__global__ void __launch_bounds__(256) k_mlp(const float* __restrict__ g,
                                             const float* __restrict__ b,
                                             const float* __restrict__ fb1,
                                             const float* __restrict__ fb2,
                                             float* __restrict__ out) {
    __shared__ __align__(16) uint32_t As[64][52];
    __shared__ __align__(16) uint32_t Hs[64][52];
    __shared__ __align__(16) uint32_t Bs[96][52];
    const int tid = threadIdx.x;
    const int wid = tid >> 5, lane = tid & 31;
    const int warp_m = wid >> 2;
    const int warp_n = wid & 3;
    const int grp = lane >> 2, qid = lane & 3;
    const int m0 = blockIdx.x * 64;

    bf16* asb = reinterpret_cast<bf16*>(As);
    for (int r = wid * 8; r < wid * 8 + 8; r++) {
        const float* xr = g_x1 + (size_t)(m0 + r) * CC;
        float v0 = xr[lane], v1 = xr[lane + 32], v2 = xr[lane + 64];
        float s = v0 + v1 + v2;
#pragma unroll
        for (int o = 16; o > 0; o >>= 1) s += __shfl_xor_sync(0xffffffffu, s, o);
        float mean = s * (1.0f / 96.0f);
        float d0 = v0 - mean, d1 = v1 - mean, d2 = v2 - mean;
        float sq = d0 * d0 + d1 * d1 + d2 * d2;
#pragma unroll
        for (int o = 16; o > 0; o >>= 1) sq += __shfl_xor_sync(0xffffffffu, sq, o);
        float rstd = rsqrtf(sq * (1.0f / 96.0f) + 1e-5f);
        asb[r * 104 + lane]      = (bf16)(d0 * rstd * g[lane]      + b[lane]);
        asb[r * 104 + lane + 32] = (bf16)(d1 * rstd * g[lane + 32] + b[lane + 32]);
        asb[r * 104 + lane + 64] = (bf16)(d2 * rstd * g[lane + 64] + b[lane + 64]);
    }
    __syncthreads();

    float c2[2][3][4];
#pragma unroll
    for (int i = 0; i < 2; i++)
#pragma unroll
        for (int j = 0; j < 3; j++)
#pragma unroll
            for (int e = 0; e < 4; e++) c2[i][j][e] = 0.f;

    for (int hc = 0; hc < 4; hc++) {
        for (int i = tid; i < 1152; i += 256) {
            int row = i / 12, c8 = i - row * 12;
            *reinterpret_cast<uint4*>(&Bs[row][c8 * 4]) =
                *reinterpret_cast<const uint4*>(g_wfc1 + (size_t)(hc * 96 + row) * 96 + c8 * 8);
        }
        __syncthreads();

        float c1[2][3][4];
#pragma unroll
        for (int i = 0; i < 2; i++)
#pragma unroll
            for (int j = 0; j < 3; j++)
#pragma unroll
                for (int e = 0; e < 4; e++) c1[i][j][e] = 0.f;
#pragma unroll
        for (int kk = 0; kk < 48; kk += 8) {
            uint32_t a[2][4], bb[3][2];
#pragma unroll
            for (int i = 0; i < 2; i++) {
                int ar = warp_m * 32 + i * 16 + grp;
                a[i][0] = As[ar][kk + qid];
                a[i][1] = As[ar + 8][kk + qid];
                a[i][2] = As[ar][kk + qid + 4];
                a[i][3] = As[ar + 8][kk + qid + 4];
            }
#pragma unroll
            for (int j = 0; j < 3; j++) {
                int br = warp_n * 24 + j * 8 + grp;
                bb[j][0] = Bs[br][kk + qid];
                bb[j][1] = Bs[br][kk + qid + 4];
            }
#pragma unroll
            for (int i = 0; i < 2; i++)
#pragma unroll
                for (int j = 0; j < 3; j++)
                    mma_bf16(c1[i][j], a[i], bb[j]);
        }

#pragma unroll
        for (int i = 0; i < 2; i++) {
            int r = warp_m * 32 + i * 16 + grp;
#pragma unroll
            for (int j = 0; j < 3; j++) {
                int cw = warp_n * 12 + j * 4 + qid;
                int n = hc * 96 + cw * 2;
                float b0 = fb1[n], b1 = fb1[n + 1];
                float a0 = c1[i][j][0] + b0, a1 = c1[i][j][1] + b1;
                float a2 = c1[i][j][2] + b0, a3 = c1[i][j][3] + b1;
                a0 = 0.5f * a0 * (1.0f + erff(a0 * 0.70710678118654752f));
                a1 = 0.5f * a1 * (1.0f + erff(a1 * 0.70710678118654752f));
                a2 = 0.5f * a2 * (1.0f + erff(a2 * 0.70710678118654752f));
                a3 = 0.5f * a3 * (1.0f + erff(a3 * 0.70710678118654752f));
                bf162 p0 = __floats2bfloat162_rn(a0, a1);
                bf162 p1 = __floats2bfloat162_rn(a2, a3);
                Hs[r][cw]     = *reinterpret_cast<uint32_t*>(&p0);
                Hs[r + 8][cw] = *reinterpret_cast<uint32_t*>(&p1);
            }
        }
        __syncthreads();

        for (int i = tid; i < 1152; i += 256) {
            int row = i / 12, c8 = i - row * 12;
            *reinterpret_cast<uint4*>(&Bs[row][c8 * 4]) =
                *reinterpret_cast<const uint4*>(g_wfc2 + (size_t)row * 384 + hc * 96 + c8 * 8);
        }
        __syncthreads();

#pragma unroll
        for (int kk = 0; kk < 48; kk += 8) {
            uint32_t a[2][4], bb[3][2];
#pragma unroll
            for (int i = 0; i < 2; i++) {
                int ar = warp_m * 32 + i * 16 + grp;
                a[i][0] = Hs[ar][kk + qid];
                a[i][1] = Hs[ar + 8][kk + qid];
                a[i][2] = Hs[ar][kk + qid + 4];
                a[i][3] = Hs[ar + 8][kk + qid + 4];
            }
#pragma unroll
            for (int j = 0; j < 3; j++) {
                int br = warp_n * 24 + j * 8 + grp;
                bb[j][0] = Bs[br][kk + qid];
                bb[j][1] = Bs[br][kk + qid + 4];
            }
#pragma unroll
            for (int i = 0; i < 2; i++)
#pragma unroll
                for (int j = 0; j < 3; j++)
                    mma_bf16(c2[i][j], a[i], bb[j]);
        }
        __syncthreads();
    }

#pragma unroll
    for (int i = 0; i < 2; i++) {
        int r = m0 + warp_m * 32 + i * 16 + grp;
#pragma unroll
        for (int j = 0; j < 3; j++) {
            int n = warp_n * 24 + j * 8 + qid * 2;
            size_t o0 = (size_t)r * CC + n;
            size_t o1 = (size_t)(r + 8) * CC + n;
            float2 x0 = *reinterpret_cast<const float2*>(g_x1 + o0);
            float2 x1v = *reinterpret_cast<const float2*>(g_x1 + o1);
            float b0 = fb2[n], b1 = fb2[n + 1];
            *reinterpret_cast<float2*>(out + o0) =
                make_float2(x0.x + c2[i][j][0] + b0, x0.y + c2[i][j][1] + b1);
            *reinterpret_cast<float2*>(out + o1) =
                make_float2(x1v.x + c2[i][j][2] + b0, x1v.y + c2[i][j][3] + b1);
        }
    }
}

// ---------------------------------------------------------------------------
// Attention: block = (window, head), 128 threads, 2 threads per row (j-split)
// ---------------------------------------------------------------------------
__global__ void __launch_bounds__(128) k_attn() {
    int bh = blockIdx.x;
    int win = bh / 3, head = bh - win * 3;
    int widx = win & 255;

    __shared__ __align__(16) float Ks[NTOK * 32];
    __shared__ __align__(16) float Vs[NTOK * 32];
    __shared__ __align__(16) float Ps[NTOK * 51];
    __shared__ __align__(16) float Qsm[NTOK * 33];

    const size_t base = (size_t)bh * (NTOK * HDD);
    const int tid = threadIdx.x;
    const int row = tid >> 1, half = tid & 1;
    const int wid = tid >> 5;

    const uint4* qp = reinterpret_cast<const uint4*>(g_qh + base);
    const uint4* kp = reinterpret_cast<const uint4*>(g_kh + base);
    const uint4* vp = reinterpret_cast<const uint4*>(g_vh + base);
    for (int idx = tid; idx < 196; idx += 128) {
        int r = idx >> 2, seg = idx & 3;
        uint4 qv = qp[idx], kv = kp[idx], vv = vp[idx];
        const bf162* q2 = reinterpret_cast<const bf162*>(&qv);
        const bf162* k2 = reinterpret_cast<const bf162*>(&kv);
        const bf162* v2 = reinterpret_cast<const bf162*>(&vv);
        float* qd = Qsm + r * 33 + seg * 8;
        float* kd = Ks + r * 32 + seg * 8;
        float* vd = Vs + r * 32 + seg * 8;
#pragma unroll
        for (int t = 0; t < 4; t++) {
            float2 f;
            f = __bfloat1622float2(q2[t]); qd[2 * t] = f.x; qd[2 * t + 1] = f.y;
            f = __bfloat1622float2(k2[t]); kd[2 * t] = f.x; kd[2 * t + 1] = f.y;
            f = __bfloat1622float2(v2[t]); vd[2 * t] = f.x; vd[2 * t + 1] = f.y;
        }
    }
    const float* cp = g_comb + (size_t)(widx * 3 + head) * (NTOK * NTOK);
    for (int idx = tid; idx < NTOK * NTOK; idx += 128) {
        int i = idx / NTOK, j = idx - i * NTOK;
        Ps[i * 51 + j] = cp[idx];
    }
    __syncthreads();

    if (row < NTOK) {
        const unsigned pmask = (wid == 3) ? 0x3u : 0xffffffffu;
        float q[32];
#pragma unroll
        for (int d = 0; d < 32; d++) q[d] = Qsm[row * 33 + d];

        const int j0 = half ? 25 : 0;
        const int j1 = half ? NTOK : 25;

        float mx = -1e30f;
        for (int j = j0; j < j1; j++) {
            float s = Ps[row * 51 + j];
            const float4* kr = reinterpret_cast<const float4*>(Ks + j * 32);
#pragma unroll
            for (int d4 = 0; d4 < 8; d4++) {
                float4 kv = kr[d4];
                s += q[4 * d4] * kv.x + q[4 * d4 + 1] * kv.y
                   + q[4 * d4 + 2] * kv.z + q[4 * d4 + 3] * kv.w;
            }
            Ps[row * 51 + j] = s;
            mx = fmaxf(mx, s);
        }
        mx = fmaxf(mx, __shfl_xor_sync(pmask, mx, 1));

        float sum = 0.f;
        for (int j = j0; j < j1; j++) {
            float e = __expf(Ps[row * 51 + j] - mx);
            Ps[row * 51 + j] = e;
            sum += e;
        }
        sum += __shfl_xor_sync(pmask, sum, 1);
        float inv = 1.0f / sum;

        float o[32];
#pragma unroll
        for (int d = 0; d < 32; d++) o[d] = 0.f;
        for (int j = j0; j < j1; j++) {
            float p = Ps[row * 51 + j];
            const float4* vr = reinterpret_cast<const float4*>(Vs + j * 32);
#pragma unroll
            for (int d4 = 0; d4 < 8; d4++) {
                float4 vv = vr[d4];
                o[4 * d4]     += p * vv.x;
                o[4 * d4 + 1] += p * vv.y;
                o[4 * d4 + 2] += p * vv.z;
                o[4 * d4 + 3] += p * vv.w;
            }
        }
#pragma unroll
        for (int d = 0; d < 32; d++) o[d] += __shfl_xor_sync(pmask, o[d], 1);

        // both halves hold the full row; each writes 16 of the 32 dims
        bf16* op = g_atth + (size_t)win * (NTOK * CC) + head * HDD + row * CC;
        int dbase = half * 16;
#pragma unroll
        for (int t = 0; t < 8; t++) {
            int d = dbase + t * 2;
            *reinterpret_cast<bf162*>(op + d) =
                __floats2bfloat162_rn(o[d] * inv, o[d + 1] * inv);
        }
    }
}

// ---------------------------------------------------------------------------
// Launch
// ---------------------------------------------------------------------------
extern "C" void kernel_launch(void* const* d_in, const int* in_sizes, int n_in,
                              void* d_out, int out_size) {
    const float* x         = (const float*)d_in[0];
    const float* attn_mask = (const float*)d_in[1];
    const int*   rel_index = (const int*)  d_in[2];
    const float* n1g       = (const float*)d_in[3];
    const float* n1b       = (const float*)d_in[4];
    const float* qkv_w     = (const float*)d_in[5];
    const float* qkv_b     = (const float*)d_in[6];
    const float* proj_w    = (const float*)d_in[7];
    const float* proj_b    = (const float*)d_in[8];
    const float* tbl       = (const float*)d_in[9];
    const float* n2g       = (const float*)d_in[10];
    const float* n2b       = (const float*)d_in[11];
    const float* fc1_w     = (const float*)d_in[12];
    const float* fc1_b     = (const float*)d_in[13];
    const float* fc2_w     = (const float*)d_in[14];
    const float* fc2_b     = (const float*)d_in[15];
    float* out = (float*)d_out;

    k_prep<<<432, 256>>>(qkv_w, proj_w, fc1_w, fc2_w);
    k_comb<<<256 * NHH, 256>>>(attn_mask, rel_index, tbl);
    k_qkv <<<MTOK / 64, 256>>>(x, n1g, n1b, qkv_b);
    k_attn<<<NWIN * NHH, 128>>>();
    k_gemm_proj<<<dim3(1, MTOK / 128), 256>>>(proj_b, x);
    k_mlp<<<MTOK / 64, 256>>>(n2g, n2b, fc1_b, fc2_b, out);
}

// round 11
// speedup vs baseline: 1.2109x; 1.2109x over previous
#include <cuda_runtime.h>
#include <cuda_bf16.h>
#include <math.h>
#include <stdint.h>

// ---------------------------------------------------------------------------
// Problem constants
// ---------------------------------------------------------------------------
#define BB    32
#define HH    112
#define WW2   112
#define CC    96
#define NHH   3
#define WSS   7
#define SHF   3
#define HIDD  384
#define NTOK  49
#define HDD   32
#define NWIN  8192
#define MTOK  401408

typedef __nv_bfloat16 bf16;
typedef __nv_bfloat162 bf162;

// ---------------------------------------------------------------------------
// Scratch (device globals)
// ---------------------------------------------------------------------------
__device__ __align__(16) bf16  g_ln1h[(size_t)MTOK * CC];
__device__ __align__(16) bf16  g_qh[(size_t)NWIN * NHH * NTOK * HDD];
__device__ __align__(16) bf16  g_kh[(size_t)NWIN * NHH * NTOK * HDD];
__device__ __align__(16) bf16  g_vh[(size_t)NWIN * NHH * NTOK * HDD];
__device__ __align__(16) bf16  g_atth[(size_t)MTOK * CC];
__device__ __align__(16) float g_x1[(size_t)MTOK * CC];
__device__ __align__(16) float g_comb[(size_t)256 * NHH * NTOK * NTOK];
__device__ __align__(16) bf16 g_wqkv[288 * 96];
__device__ __align__(16) bf16 g_wproj[96 * 96];
__device__ __align__(16) bf16 g_wfc1[384 * 96];
__device__ __align__(16) bf16 g_wfc2[96 * 384];

__device__ __forceinline__ int rowsrc(int m) {
    int win = m / NTOK, tok = m - win * NTOK;
    int b = win >> 8, widx = win & 255;
    int wh = widx >> 4, ww = widx & 15;
    int r = tok / WSS, c = tok - r * WSS;
    int h = wh * WSS + r + SHF; if (h >= HH) h -= HH;
    int w = ww * WSS + c + SHF; if (w >= WW2) w -= WW2;
    return (b * HH + h) * WW2 + w;
}

// ---------------------------------------------------------------------------
// Weight conversion
// ---------------------------------------------------------------------------
__global__ void __launch_bounds__(256) k_prep(const float* __restrict__ qkvw,
                                              const float* __restrict__ projw,
                                              const float* __restrict__ fc1w,
                                              const float* __restrict__ fc2w) {
    int i = blockIdx.x * 256 + threadIdx.x;
    if (i < 27648)               g_wqkv[i]           = __float2bfloat16(qkvw[i]);
    else if (i < 27648 + 9216)   g_wproj[i - 27648]  = __float2bfloat16(projw[i - 27648]);
    else if (i < 36864 + 36864)  g_wfc1[i - 36864]   = __float2bfloat16(fc1w[i - 36864]);
    else if (i < 110592)         g_wfc2[i - 73728]   = __float2bfloat16(fc2w[i - 73728]);
}

// ---------------------------------------------------------------------------
// LayerNorm1 (warp per token, gathered)
// ---------------------------------------------------------------------------
__global__ void __launch_bounds__(256) k_ln1(const float* __restrict__ x,
                                             const float* __restrict__ g,
                                             const float* __restrict__ b) {
    int m = blockIdx.x * 8 + (threadIdx.x >> 5);
    int lane = threadIdx.x & 31;
    int src = rowsrc(m);
    const float* xr = x + (size_t)src * CC;
    float v0 = xr[lane], v1 = xr[lane + 32], v2 = xr[lane + 64];
    float s = v0 + v1 + v2;
#pragma unroll
    for (int o = 16; o > 0; o >>= 1) s += __shfl_xor_sync(0xffffffffu, s, o);
    float mean = s * (1.0f / 96.0f);
    float d0 = v0 - mean, d1 = v1 - mean, d2 = v2 - mean;
    float sq = d0 * d0 + d1 * d1 + d2 * d2;
#pragma unroll
    for (int o = 16; o > 0; o >>= 1) sq += __shfl_xor_sync(0xffffffffu, sq, o);
    float rstd = rsqrtf(sq * (1.0f / 96.0f) + 1e-5f);
    bf16* orow = g_ln1h + (size_t)m * CC;
    orow[lane]      = (bf16)(d0 * rstd * g[lane]      + b[lane]);
    orow[lane + 32] = (bf16)(d1 * rstd * g[lane + 32] + b[lane + 32]);
    orow[lane + 64] = (bf16)(d2 * rstd * g[lane + 64] + b[lane + 64]);
}

// ---------------------------------------------------------------------------
// Combined additive bias
// ---------------------------------------------------------------------------
__global__ void __launch_bounds__(256) k_comb(const float* __restrict__ mask,
                                              const int* __restrict__ ridx,
                                              const float* __restrict__ table) {
    int wh = blockIdx.x;
    int widx = wh / 3, head = wh - widx * 3;
    const int NN = NTOK * NTOK;
    float* dst = g_comb + (size_t)wh * NN;
    const float* msk = mask + (size_t)widx * NN;
    for (int idx = threadIdx.x; idx < NN; idx += 256)
        dst[idx] = msk[idx] + table[ridx[idx] * NHH + head];
}

// ---------------------------------------------------------------------------
// BF16 mma helper
// ---------------------------------------------------------------------------
__device__ __forceinline__ void mma_bf16(float* c, const uint32_t* a, const uint32_t* b) {
    asm volatile(
        "mma.sync.aligned.m16n8k16.row.col.f32.bf16.bf16.f32 "
        "{%0,%1,%2,%3}, {%4,%5,%6,%7}, {%8,%9}, {%0,%1,%2,%3};"
        : "+f"(c[0]), "+f"(c[1]), "+f"(c[2]), "+f"(c[3])
        : "r"(a[0]), "r"(a[1]), "r"(a[2]), "r"(a[3]), "r"(b[0]), "r"(b[1]));
}

// ---------------------------------------------------------------------------
// BF16 tensor-core GEMM: 128x96 tile, BK=96, 8 warps (4m x 2n)
// ---------------------------------------------------------------------------
template <int K, typename Epi>
__device__ __forceinline__ void gemm_body(const bf16* __restrict__ A,
                                          const bf16* __restrict__ W,
                                          Epi epi) {
    constexpr int BK = 96;
    constexpr int KP = 48;
    constexpr int ST = 52;
    __shared__ __align__(16) uint32_t As[128][ST];
    __shared__ __align__(16) uint32_t Bs[96][ST];
    const int tid = threadIdx.x;
    const int wid = tid >> 5, lane = tid & 31;
    const int warp_m = wid >> 1, warp_n = wid & 1;
    const int grp = lane >> 2, qid = lane & 3;
    const int m0 = blockIdx.y * 128;
    const int n0 = blockIdx.x * 96;

    float c[2][6][4];
#pragma unroll
    for (int i = 0; i < 2; i++)
#pragma unroll
        for (int j = 0; j < 6; j++)
#pragma unroll
            for (int e = 0; e < 4; e++) c[i][j][e] = 0.f;

    for (int k0 = 0; k0 < K; k0 += BK) {
#pragma unroll
        for (int i = 0; i < 6; i++) {
            int idx = tid + i * 256;
            int row = idx / 12, c8 = idx - row * 12;
            uint4 v = *reinterpret_cast<const uint4*>(A + (size_t)(m0 + row) * K + k0 + c8 * 8);
            *reinterpret_cast<uint4*>(&As[row][c8 * 4]) = v;
        }
#pragma unroll
        for (int i = 0; i < 5; i++) {
            int idx = tid + i * 256;
            if (idx < 1152) {
                int row = idx / 12, c8 = idx - row * 12;
                uint4 v = *reinterpret_cast<const uint4*>(W + (size_t)(n0 + row) * K + k0 + c8 * 8);
                *reinterpret_cast<uint4*>(&Bs[row][c8 * 4]) = v;
            }
        }
        __syncthreads();

#pragma unroll
        for (int kk = 0; kk < KP; kk += 8) {
            uint32_t a[2][4], b[6][2];
#pragma unroll
            for (int i = 0; i < 2; i++) {
                int ar = warp_m * 32 + i * 16 + grp;
                a[i][0] = As[ar][kk + qid];
                a[i][1] = As[ar + 8][kk + qid];
                a[i][2] = As[ar][kk + qid + 4];
                a[i][3] = As[ar + 8][kk + qid + 4];
            }
#pragma unroll
            for (int j = 0; j < 6; j++) {
                int br = warp_n * 48 + j * 8 + grp;
                b[j][0] = Bs[br][kk + qid];
                b[j][1] = Bs[br][kk + qid + 4];
            }
#pragma unroll
            for (int i = 0; i < 2; i++)
#pragma unroll
                for (int j = 0; j < 6; j++)
                    mma_bf16(c[i][j], a[i], b[j]);
        }
        __syncthreads();
    }

#pragma unroll
    for (int i = 0; i < 2; i++) {
        int r0 = m0 + warp_m * 32 + i * 16 + grp;
#pragma unroll
        for (int j = 0; j < 6; j++) {
            int cn = n0 + warp_n * 48 + j * 8 + qid * 2;
            epi(r0,     cn, c[i][j][0], c[i][j][1]);
            epi(r0 + 8, cn, c[i][j][2], c[i][j][3]);
        }
    }
}

// ------------------------- epilogues ---------------------------------------
struct QkvEpi {
    const float* bias;
    __device__ void operator()(int m, int n, float v0, float v1) const {
        float a = v0 + bias[n], b = v1 + bias[n + 1];
        int which = n / 96; int rem = n - which * 96;
        int head = rem >> 5; int d = rem & 31;
        int win = m / NTOK; int tok = m - win * NTOK;
        size_t off = ((size_t)(win * 3 + head) * NTOK + tok) * HDD + d;
        if (which == 0) {
            a *= 0.17677669529663689f; b *= 0.17677669529663689f;
            *reinterpret_cast<bf162*>(g_qh + off) = __floats2bfloat162_rn(a, b);
        } else if (which == 1) {
            *reinterpret_cast<bf162*>(g_kh + off) = __floats2bfloat162_rn(a, b);
        } else {
            *reinterpret_cast<bf162*>(g_vh + off) = __floats2bfloat162_rn(a, b);
        }
    }
};

struct ProjEpi {
    const float* x;
    const float* pb;
    __device__ void operator()(int m, int n, float v0, float v1) const {
        int src = rowsrc(m);
        size_t o = (size_t)src * CC + n;
        float2 xv = *reinterpret_cast<const float2*>(x + o);
        float2 r = make_float2(xv.x + v0 + pb[n], xv.y + v1 + pb[n + 1]);
        *reinterpret_cast<float2*>(g_x1 + o) = r;
    }
};

// ------------------------- GEMM wrappers -----------------------------------
__global__ void __launch_bounds__(256) k_gemm_qkv(const float* __restrict__ bias) {
    gemm_body<96>(g_ln1h, g_wqkv, QkvEpi{bias});
}
__global__ void __launch_bounds__(256) k_gemm_proj(const float* __restrict__ pb,
                                                   const float* __restrict__ x) {
    gemm_body<96>(g_atth, g_wproj, ProjEpi{x, pb});
}

// ---------------------------------------------------------------------------
// Fused MLP: LN2 + fc1 + GELU + fc2 + residual.  64 rows/block, 256 threads.
// ---------------------------------------------------------------------------
__global__ void __launch_bounds__(256) k_mlp(const float* __restrict__ g,
                                             const float* __restrict__ b,
                                             const float* __restrict__ fb1,
                                             const float* __restrict__ fb2,
                                             float* __restrict__ out) {
    __shared__ __align__(16) uint32_t As[64][52];
    __shared__ __align__(16) uint32_t Hs[64][52];
    __shared__ __align__(16) uint32_t Bs[96][52];
    const int tid = threadIdx.x;
    const int wid = tid >> 5, lane = tid & 31;
    const int warp_m = wid >> 2;
    const int warp_n = wid & 3;
    const int grp = lane >> 2, qid = lane & 3;
    const int m0 = blockIdx.x * 64;

    bf16* asb = reinterpret_cast<bf16*>(As);
    for (int r = wid * 8; r < wid * 8 + 8; r++) {
        const float* xr = g_x1 + (size_t)(m0 + r) * CC;
        float v0 = xr[lane], v1 = xr[lane + 32], v2 = xr[lane + 64];
        float s = v0 + v1 + v2;
#pragma unroll
        for (int o = 16; o > 0; o >>= 1) s += __shfl_xor_sync(0xffffffffu, s, o);
        float mean = s * (1.0f / 96.0f);
        float d0 = v0 - mean, d1 = v1 - mean, d2 = v2 - mean;
        float sq = d0 * d0 + d1 * d1 + d2 * d2;
#pragma unroll
        for (int o = 16; o > 0; o >>= 1) sq += __shfl_xor_sync(0xffffffffu, sq, o);
        float rstd = rsqrtf(sq * (1.0f / 96.0f) + 1e-5f);
        asb[r * 104 + lane]      = (bf16)(d0 * rstd * g[lane]      + b[lane]);
        asb[r * 104 + lane + 32] = (bf16)(d1 * rstd * g[lane + 32] + b[lane + 32]);
        asb[r * 104 + lane + 64] = (bf16)(d2 * rstd * g[lane + 64] + b[lane + 64]);
    }
    __syncthreads();

    float c2[2][3][4];
#pragma unroll
    for (int i = 0; i < 2; i++)
#pragma unroll
        for (int j = 0; j < 3; j++)
#pragma unroll
            for (int e = 0; e < 4; e++) c2[i][j][e] = 0.f;

    for (int hc = 0; hc < 4; hc++) {
        for (int i = tid; i < 1152; i += 256) {
            int row = i / 12, c8 = i - row * 12;
            *reinterpret_cast<uint4*>(&Bs[row][c8 * 4]) =
                *reinterpret_cast<const uint4*>(g_wfc1 + (size_t)(hc * 96 + row) * 96 + c8 * 8);
        }
        __syncthreads();

        float c1[2][3][4];
#pragma unroll
        for (int i = 0; i < 2; i++)
#pragma unroll
            for (int j = 0; j < 3; j++)
#pragma unroll
                for (int e = 0; e < 4; e++) c1[i][j][e] = 0.f;
#pragma unroll
        for (int kk = 0; kk < 48; kk += 8) {
            uint32_t a[2][4], bb[3][2];
#pragma unroll
            for (int i = 0; i < 2; i++) {
                int ar = warp_m * 32 + i * 16 + grp;
                a[i][0] = As[ar][kk + qid];
                a[i][1] = As[ar + 8][kk + qid];
                a[i][2] = As[ar][kk + qid + 4];
                a[i][3] = As[ar + 8][kk + qid + 4];
            }
#pragma unroll
            for (int j = 0; j < 3; j++) {
                int br = warp_n * 24 + j * 8 + grp;
                bb[j][0] = Bs[br][kk + qid];
                bb[j][1] = Bs[br][kk + qid + 4];
            }
#pragma unroll
            for (int i = 0; i < 2; i++)
#pragma unroll
                for (int j = 0; j < 3; j++)
                    mma_bf16(c1[i][j], a[i], bb[j]);
        }

#pragma unroll
        for (int i = 0; i < 2; i++) {
            int r = warp_m * 32 + i * 16 + grp;
#pragma unroll
            for (int j = 0; j < 3; j++) {
                int cw = warp_n * 12 + j * 4 + qid;
                int n = hc * 96 + cw * 2;
                float b0 = fb1[n], b1 = fb1[n + 1];
                float a0 = c1[i][j][0] + b0, a1 = c1[i][j][1] + b1;
                float a2 = c1[i][j][2] + b0, a3 = c1[i][j][3] + b1;
                a0 = 0.5f * a0 * (1.0f + erff(a0 * 0.70710678118654752f));
                a1 = 0.5f * a1 * (1.0f + erff(a1 * 0.70710678118654752f));
                a2 = 0.5f * a2 * (1.0f + erff(a2 * 0.70710678118654752f));
                a3 = 0.5f * a3 * (1.0f + erff(a3 * 0.70710678118654752f));
                bf162 p0 = __floats2bfloat162_rn(a0, a1);
                bf162 p1 = __floats2bfloat162_rn(a2, a3);
                Hs[r][cw]     = *reinterpret_cast<uint32_t*>(&p0);
                Hs[r + 8][cw] = *reinterpret_cast<uint32_t*>(&p1);
            }
        }
        __syncthreads();

        for (int i = tid; i < 1152; i += 256) {
            int row = i / 12, c8 = i - row * 12;
            *reinterpret_cast<uint4*>(&Bs[row][c8 * 4]) =
                *reinterpret_cast<const uint4*>(g_wfc2 + (size_t)row * 384 + hc * 96 + c8 * 8);
        }
        __syncthreads();

#pragma unroll
        for (int kk = 0; kk < 48; kk += 8) {
            uint32_t a[2][4], bb[3][2];
#pragma unroll
            for (int i = 0; i < 2; i++) {
                int ar = warp_m * 32 + i * 16 + grp;
                a[i][0] = Hs[ar][kk + qid];
                a[i][1] = Hs[ar + 8][kk + qid];
                a[i][2] = Hs[ar][kk + qid + 4];
                a[i][3] = Hs[ar + 8][kk + qid + 4];
            }
#pragma unroll
            for (int j = 0; j < 3; j++) {
                int br = warp_n * 24 + j * 8 + grp;
                bb[j][0] = Bs[br][kk + qid];
                bb[j][1] = Bs[br][kk + qid + 4];
            }
#pragma unroll
            for (int i = 0; i < 2; i++)
#pragma unroll
                for (int j = 0; j < 3; j++)
                    mma_bf16(c2[i][j], a[i], bb[j]);
        }
        __syncthreads();
    }

#pragma unroll
    for (int i = 0; i < 2; i++) {
        int r = m0 + warp_m * 32 + i * 16 + grp;
#pragma unroll
        for (int j = 0; j < 3; j++) {
            int n = warp_n * 24 + j * 8 + qid * 2;
            size_t o0 = (size_t)r * CC + n;
            size_t o1 = (size_t)(r + 8) * CC + n;
            float2 x0 = *reinterpret_cast<const float2*>(g_x1 + o0);
            float2 x1v = *reinterpret_cast<const float2*>(g_x1 + o1);
            float b0 = fb2[n], b1 = fb2[n + 1];
            *reinterpret_cast<float2*>(out + o0) =
                make_float2(x0.x + c2[i][j][0] + b0, x0.y + c2[i][j][1] + b1);
            *reinterpret_cast<float2*>(out + o1) =
                make_float2(x1v.x + c2[i][j][2] + b0, x1v.y + c2[i][j][3] + b1);
        }
    }
}

// ---------------------------------------------------------------------------
// Attention: block = (window, head), 64 threads, online softmax (single pass)
// smem = Qs 6.5KB + Ks 6.3KB + Vs 6.3KB = 19KB (no score buffer)
// ---------------------------------------------------------------------------
__global__ void __launch_bounds__(64) k_attn() {
    int bh = blockIdx.x;
    int win = bh / 3, head = bh - win * 3;
    int widx = win & 255;

    __shared__ __align__(16) float Ks[NTOK * 32];
    __shared__ __align__(16) float Vs[NTOK * 32];
    __shared__ __align__(16) float Qs[NTOK * 33];   // Q staging, then output staging

    const size_t base = (size_t)bh * (NTOK * HDD);
    const int tid = threadIdx.x;

    const uint4* qp = reinterpret_cast<const uint4*>(g_qh + base);
    const uint4* kp = reinterpret_cast<const uint4*>(g_kh + base);
    const uint4* vp = reinterpret_cast<const uint4*>(g_vh + base);
    for (int idx = tid; idx < 196; idx += 64) {
        int row = idx >> 2, seg = idx & 3;
        uint4 qv = qp[idx], kv = kp[idx], vv = vp[idx];
        const bf162* q2 = reinterpret_cast<const bf162*>(&qv);
        const bf162* k2 = reinterpret_cast<const bf162*>(&kv);
        const bf162* v2 = reinterpret_cast<const bf162*>(&vv);
        float* qd = Qs + row * 33 + seg * 8;
        float* kd = Ks + row * 32 + seg * 8;
        float* vd = Vs + row * 32 + seg * 8;
#pragma unroll
        for (int t = 0; t < 4; t++) {
            float2 f;
            f = __bfloat1622float2(q2[t]); qd[2 * t] = f.x; qd[2 * t + 1] = f.y;
            f = __bfloat1622float2(k2[t]); kd[2 * t] = f.x; kd[2 * t + 1] = f.y;
            f = __bfloat1622float2(v2[t]); vd[2 * t] = f.x; vd[2 * t + 1] = f.y;
        }
    }
    __syncthreads();

    const int i = tid;
    float inv = 0.f;
    float o[32];
    if (i < NTOK) {
        float q[32];
#pragma unroll
        for (int d = 0; d < 32; d++) q[d] = Qs[i * 33 + d];
        const float* cb = g_comb + (size_t)(widx * 3 + head) * (NTOK * NTOK) + i * NTOK;

        float mx = -1e30f, sum = 0.f;
#pragma unroll
        for (int d = 0; d < 32; d++) o[d] = 0.f;

        for (int j = 0; j < NTOK; j++) {
            float s = cb[j];
            const float4* kr = reinterpret_cast<const float4*>(Ks + j * 32);
#pragma unroll
            for (int d4 = 0; d4 < 8; d4++) {
                float4 kv = kr[d4];
                s += q[4 * d4] * kv.x + q[4 * d4 + 1] * kv.y
                   + q[4 * d4 + 2] * kv.z + q[4 * d4 + 3] * kv.w;
            }
            if (s > mx) {                       // rescale (rare)
                float corr = __expf(mx - s);
                sum *= corr;
#pragma unroll
                for (int d = 0; d < 32; d++) o[d] *= corr;
                mx = s;
            }
            float e = __expf(s - mx);
            sum += e;
            const float4* vr = reinterpret_cast<const float4*>(Vs + j * 32);
#pragma unroll
            for (int d4 = 0; d4 < 8; d4++) {
                float4 vv = vr[d4];
                o[4 * d4]     += e * vv.x;
                o[4 * d4 + 1] += e * vv.y;
                o[4 * d4 + 2] += e * vv.z;
                o[4 * d4 + 3] += e * vv.w;
            }
        }
        inv = 1.0f / sum;
    }
    __syncthreads();      // staging loads fully consumed before Qs reuse
    if (i < NTOK) {
#pragma unroll
        for (int d = 0; d < 32; d++) Qs[i * 33 + d] = o[d] * inv;
    }
    __syncthreads();

    bf16* op = g_atth + (size_t)win * (NTOK * CC) + head * HDD;
    for (int idx = tid; idx < NTOK * 16; idx += 64) {
        int i2 = idx >> 4, dp = idx & 15;
        float a = Qs[i2 * 33 + dp * 2], b = Qs[i2 * 33 + dp * 2 + 1];
        *reinterpret_cast<bf162*>(op + i2 * CC + dp * 2) = __floats2bfloat162_rn(a, b);
    }
}

// ---------------------------------------------------------------------------
// Launch
// ---------------------------------------------------------------------------
extern "C" void kernel_launch(void* const* d_in, const int* in_sizes, int n_in,
                              void* d_out, int out_size) {
    const float* x         = (const float*)d_in[0];
    const float* attn_mask = (const float*)d_in[1];
    const int*   rel_index = (const int*)  d_in[2];
    const float* n1g       = (const float*)d_in[3];
    const float* n1b       = (const float*)d_in[4];
    const float* qkv_w     = (const float*)d_in[5];
    const float* qkv_b     = (const float*)d_in[6];
    const float* proj_w    = (const float*)d_in[7];
    const float* proj_b    = (const float*)d_in[8];
    const float* tbl       = (const float*)d_in[9];
    const float* n2g       = (const float*)d_in[10];
    const float* n2b       = (const float*)d_in[11];
    const float* fc1_w     = (const float*)d_in[12];
    const float* fc1_b     = (const float*)d_in[13];
    const float* fc2_w     = (const float*)d_in[14];
    const float* fc2_b     = (const float*)d_in[15];
    float* out = (float*)d_out;

    k_prep<<<432, 256>>>(qkv_w, proj_w, fc1_w, fc2_w);
    k_ln1 <<<MTOK / 8, 256>>>(x, n1g, n1b);
    k_comb<<<256 * NHH, 256>>>(attn_mask, rel_index, tbl);
    k_gemm_qkv <<<dim3(3, MTOK / 128), 256>>>(qkv_b);
    k_attn<<<NWIN * NHH, 64>>>();
    k_gemm_proj<<<dim3(1, MTOK / 128), 256>>>(proj_b, x);
    k_mlp<<<MTOK / 64, 256>>>(n2g, n2b, fc1_b, fc2_b, out);
}

// round 12
// speedup vs baseline: 1.2920x; 1.0670x over previous
#include <cuda_runtime.h>
#include <cuda_bf16.h>
#include <math.h>
#include <stdint.h>

// ---------------------------------------------------------------------------
// Problem constants
// ---------------------------------------------------------------------------
#define BB    32
#define HH    112
#define WW2   112
#define CC    96
#define NHH   3
#define WSS   7
#define SHF   3
#define HIDD  384
#define NTOK  49
#define HDD   32
#define NWIN  8192
#define MTOK  401408

typedef __nv_bfloat16 bf16;
typedef __nv_bfloat162 bf162;

// ---------------------------------------------------------------------------
// Scratch (device globals)
// ---------------------------------------------------------------------------
__device__ __align__(16) bf16  g_ln1h[(size_t)MTOK * CC];
__device__ __align__(16) bf16  g_qh[(size_t)NWIN * NHH * NTOK * HDD];
__device__ __align__(16) bf16  g_kh[(size_t)NWIN * NHH * NTOK * HDD];
__device__ __align__(16) bf16  g_vh[(size_t)NWIN * NHH * NTOK * HDD];
__device__ __align__(16) bf16  g_atth[(size_t)MTOK * CC];
__device__ __align__(16) float g_x1[(size_t)MTOK * CC];
__device__ __align__(16) float g_comb[(size_t)256 * NHH * NTOK * NTOK];
__device__ __align__(16) bf16 g_wqkv[288 * 96];
__device__ __align__(16) bf16 g_wproj[96 * 96];
__device__ __align__(16) bf16 g_wfc1[384 * 96];
__device__ __align__(16) bf16 g_wfc2[96 * 384];

__device__ __forceinline__ int rowsrc(int m) {
    int win = m / NTOK, tok = m - win * NTOK;
    int b = win >> 8, widx = win & 255;
    int wh = widx >> 4, ww = widx & 15;
    int r = tok / WSS, c = tok - r * WSS;
    int h = wh * WSS + r + SHF; if (h >= HH) h -= HH;
    int w = ww * WSS + c + SHF; if (w >= WW2) w -= WW2;
    return (b * HH + h) * WW2 + w;
}

// ---------------------------------------------------------------------------
// Weight conversion
// ---------------------------------------------------------------------------
__global__ void __launch_bounds__(256) k_prep(const float* __restrict__ qkvw,
                                              const float* __restrict__ projw,
                                              const float* __restrict__ fc1w,
                                              const float* __restrict__ fc2w) {
    int i = blockIdx.x * 256 + threadIdx.x;
    if (i < 27648)               g_wqkv[i]           = __float2bfloat16(qkvw[i]);
    else if (i < 27648 + 9216)   g_wproj[i - 27648]  = __float2bfloat16(projw[i - 27648]);
    else if (i < 36864 + 36864)  g_wfc1[i - 36864]   = __float2bfloat16(fc1w[i - 36864]);
    else if (i < 110592)         g_wfc2[i - 73728]   = __float2bfloat16(fc2w[i - 73728]);
}

// ---------------------------------------------------------------------------
// LayerNorm1 (warp per token, gathered)
// ---------------------------------------------------------------------------
__global__ void __launch_bounds__(256) k_ln1(const float* __restrict__ x,
                                             const float* __restrict__ g,
                                             const float* __restrict__ b) {
    int m = blockIdx.x * 8 + (threadIdx.x >> 5);
    int lane = threadIdx.x & 31;
    int src = rowsrc(m);
    const float* xr = x + (size_t)src * CC;
    float v0 = xr[lane], v1 = xr[lane + 32], v2 = xr[lane + 64];
    float s = v0 + v1 + v2;
#pragma unroll
    for (int o = 16; o > 0; o >>= 1) s += __shfl_xor_sync(0xffffffffu, s, o);
    float mean = s * (1.0f / 96.0f);
    float d0 = v0 - mean, d1 = v1 - mean, d2 = v2 - mean;
    float sq = d0 * d0 + d1 * d1 + d2 * d2;
#pragma unroll
    for (int o = 16; o > 0; o >>= 1) sq += __shfl_xor_sync(0xffffffffu, sq, o);
    float rstd = rsqrtf(sq * (1.0f / 96.0f) + 1e-5f);
    bf16* orow = g_ln1h + (size_t)m * CC;
    orow[lane]      = (bf16)(d0 * rstd * g[lane]      + b[lane]);
    orow[lane + 32] = (bf16)(d1 * rstd * g[lane + 32] + b[lane + 32]);
    orow[lane + 64] = (bf16)(d2 * rstd * g[lane + 64] + b[lane + 64]);
}

// ---------------------------------------------------------------------------
// Combined additive bias
// ---------------------------------------------------------------------------
__global__ void __launch_bounds__(256) k_comb(const float* __restrict__ mask,
                                              const int* __restrict__ ridx,
                                              const float* __restrict__ table) {
    int wh = blockIdx.x;
    int widx = wh / 3, head = wh - widx * 3;
    const int NN = NTOK * NTOK;
    float* dst = g_comb + (size_t)wh * NN;
    const float* msk = mask + (size_t)widx * NN;
    for (int idx = threadIdx.x; idx < NN; idx += 256)
        dst[idx] = msk[idx] + table[ridx[idx] * NHH + head];
}

// ---------------------------------------------------------------------------
// mma / ldmatrix helpers
// ---------------------------------------------------------------------------
__device__ __forceinline__ void mma_bf16(float* c, const uint32_t* a, const uint32_t* b) {
    asm volatile(
        "mma.sync.aligned.m16n8k16.row.col.f32.bf16.bf16.f32 "
        "{%0,%1,%2,%3}, {%4,%5,%6,%7}, {%8,%9}, {%0,%1,%2,%3};"
        : "+f"(c[0]), "+f"(c[1]), "+f"(c[2]), "+f"(c[3])
        : "r"(a[0]), "r"(a[1]), "r"(a[2]), "r"(a[3]), "r"(b[0]), "r"(b[1]));
}

__device__ __forceinline__ uint32_t cvta_s(const void* p) {
    return (uint32_t)__cvta_generic_to_shared(p);
}
__device__ __forceinline__ void ldsm4(uint32_t* r, uint32_t addr) {
    asm volatile("ldmatrix.sync.aligned.m8n8.x4.shared.b16 {%0,%1,%2,%3}, [%4];"
                 : "=r"(r[0]), "=r"(r[1]), "=r"(r[2]), "=r"(r[3]) : "r"(addr));
}
__device__ __forceinline__ void ldsm2(uint32_t* r, uint32_t addr) {
    asm volatile("ldmatrix.sync.aligned.m8n8.x2.shared.b16 {%0,%1}, [%2];"
                 : "=r"(r[0]), "=r"(r[1]) : "r"(addr));
}

// ---------------------------------------------------------------------------
// BF16 tensor-core GEMM: 128x96 tile, BK=96, 8 warps (4m x 2n), ldmatrix frags
// ---------------------------------------------------------------------------
template <int K, typename Epi>
__device__ __forceinline__ void gemm_body(const bf16* __restrict__ A,
                                          const bf16* __restrict__ W,
                                          Epi epi) {
    constexpr int BK = 96;
    constexpr int KP = 48;
    constexpr int ST = 52;
    __shared__ __align__(16) uint32_t As[128][ST];
    __shared__ __align__(16) uint32_t Bs[96][ST];
    const int tid = threadIdx.x;
    const int wid = tid >> 5, lane = tid & 31;
    const int warp_m = wid >> 1, warp_n = wid & 1;
    const int grp = lane >> 2, qid = lane & 3;
    const int m0 = blockIdx.y * 128;
    const int n0 = blockIdx.x * 96;
    const int lrow = lane & 15;                 // ldmatrix row within 16-strip
    const int lcol = (lane >> 4) * 4;           // word offset (k half)

    float c[2][6][4];
#pragma unroll
    for (int i = 0; i < 2; i++)
#pragma unroll
        for (int j = 0; j < 6; j++)
#pragma unroll
            for (int e = 0; e < 4; e++) c[i][j][e] = 0.f;

    for (int k0 = 0; k0 < K; k0 += BK) {
#pragma unroll
        for (int i = 0; i < 6; i++) {
            int idx = tid + i * 256;
            int row = idx / 12, c8 = idx - row * 12;
            uint4 v = *reinterpret_cast<const uint4*>(A + (size_t)(m0 + row) * K + k0 + c8 * 8);
            *reinterpret_cast<uint4*>(&As[row][c8 * 4]) = v;
        }
#pragma unroll
        for (int i = 0; i < 5; i++) {
            int idx = tid + i * 256;
            if (idx < 1152) {
                int row = idx / 12, c8 = idx - row * 12;
                uint4 v = *reinterpret_cast<const uint4*>(W + (size_t)(n0 + row) * K + k0 + c8 * 8);
                *reinterpret_cast<uint4*>(&Bs[row][c8 * 4]) = v;
            }
        }
        __syncthreads();

        uint32_t a_base[2], b_base[3];
#pragma unroll
        for (int i = 0; i < 2; i++)
            a_base[i] = cvta_s(&As[warp_m * 32 + i * 16 + lrow][lcol]);
#pragma unroll
        for (int jp = 0; jp < 3; jp++)
            b_base[jp] = cvta_s(&Bs[warp_n * 48 + jp * 16 + lrow][lcol]);

#pragma unroll
        for (int kk = 0; kk < KP; kk += 8) {
            uint32_t a[2][4], bfr[3][4];
#pragma unroll
            for (int i = 0; i < 2; i++) ldsm4(a[i], a_base[i] + kk * 4);
#pragma unroll
            for (int jp = 0; jp < 3; jp++) ldsm4(bfr[jp], b_base[jp] + kk * 4);
#pragma unroll
            for (int i = 0; i < 2; i++)
#pragma unroll
                for (int j = 0; j < 6; j++) {
                    uint32_t bb[2] = { bfr[j >> 1][j & 1], bfr[j >> 1][2 + (j & 1)] };
                    mma_bf16(c[i][j], a[i], bb);
                }
        }
        __syncthreads();
    }

#pragma unroll
    for (int i = 0; i < 2; i++) {
        int r0 = m0 + warp_m * 32 + i * 16 + grp;
#pragma unroll
        for (int j = 0; j < 6; j++) {
            int cn = n0 + warp_n * 48 + j * 8 + qid * 2;
            epi(r0,     cn, c[i][j][0], c[i][j][1]);
            epi(r0 + 8, cn, c[i][j][2], c[i][j][3]);
        }
    }
}

// ------------------------- epilogues ---------------------------------------
struct QkvEpi {
    const float* bias;
    __device__ void operator()(int m, int n, float v0, float v1) const {
        float a = v0 + bias[n], b = v1 + bias[n + 1];
        int which = n / 96; int rem = n - which * 96;
        int head = rem >> 5; int d = rem & 31;
        int win = m / NTOK; int tok = m - win * NTOK;
        size_t off = ((size_t)(win * 3 + head) * NTOK + tok) * HDD + d;
        if (which == 0) {
            a *= 0.17677669529663689f; b *= 0.17677669529663689f;
            *reinterpret_cast<bf162*>(g_qh + off) = __floats2bfloat162_rn(a, b);
        } else if (which == 1) {
            *reinterpret_cast<bf162*>(g_kh + off) = __floats2bfloat162_rn(a, b);
        } else {
            *reinterpret_cast<bf162*>(g_vh + off) = __floats2bfloat162_rn(a, b);
        }
    }
};

struct ProjEpi {
    const float* x;
    const float* pb;
    __device__ void operator()(int m, int n, float v0, float v1) const {
        int src = rowsrc(m);
        size_t o = (size_t)src * CC + n;
        float2 xv = *reinterpret_cast<const float2*>(x + o);
        float2 r = make_float2(xv.x + v0 + pb[n], xv.y + v1 + pb[n + 1]);
        *reinterpret_cast<float2*>(g_x1 + o) = r;
    }
};

// ------------------------- GEMM wrappers -----------------------------------
__global__ void __launch_bounds__(256) k_gemm_qkv(const float* __restrict__ bias) {
    gemm_body<96>(g_ln1h, g_wqkv, QkvEpi{bias});
}
__global__ void __launch_bounds__(256) k_gemm_proj(const float* __restrict__ pb,
                                                   const float* __restrict__ x) {
    gemm_body<96>(g_atth, g_wproj, ProjEpi{x, pb});
}

// ---------------------------------------------------------------------------
// Fused MLP: LN2 + fc1 + GELU + fc2 + residual.  64 rows/block, 256 threads.
// ---------------------------------------------------------------------------
__global__ void __launch_bounds__(256) k_mlp(const float* __restrict__ g,
                                             const float* __restrict__ b,
                                             const float* __restrict__ fb1,
                                             const float* __restrict__ fb2,
                                             float* __restrict__ out) {
    __shared__ __align__(16) uint32_t As[64][52];
    __shared__ __align__(16) uint32_t Hs[64][52];
    __shared__ __align__(16) uint32_t Bs[96][52];
    const int tid = threadIdx.x;
    const int wid = tid >> 5, lane = tid & 31;
    const int warp_m = wid >> 2;
    const int warp_n = wid & 3;
    const int grp = lane >> 2, qid = lane & 3;
    const int m0 = blockIdx.x * 64;
    const int lrow = lane & 15;
    const int lcol = (lane >> 4) * 4;
    const int lrow2 = lane & 7;                 // for ldsm2
    const int lcol2 = ((lane >> 3) & 1) * 4;

    bf16* asb = reinterpret_cast<bf16*>(As);
    for (int r = wid * 8; r < wid * 8 + 8; r++) {
        const float* xr = g_x1 + (size_t)(m0 + r) * CC;
        float v0 = xr[lane], v1 = xr[lane + 32], v2 = xr[lane + 64];
        float s = v0 + v1 + v2;
#pragma unroll
        for (int o = 16; o > 0; o >>= 1) s += __shfl_xor_sync(0xffffffffu, s, o);
        float mean = s * (1.0f / 96.0f);
        float d0 = v0 - mean, d1 = v1 - mean, d2 = v2 - mean;
        float sq = d0 * d0 + d1 * d1 + d2 * d2;
#pragma unroll
        for (int o = 16; o > 0; o >>= 1) sq += __shfl_xor_sync(0xffffffffu, sq, o);
        float rstd = rsqrtf(sq * (1.0f / 96.0f) + 1e-5f);
        asb[r * 104 + lane]      = (bf16)(d0 * rstd * g[lane]      + b[lane]);
        asb[r * 104 + lane + 32] = (bf16)(d1 * rstd * g[lane + 32] + b[lane + 32]);
        asb[r * 104 + lane + 64] = (bf16)(d2 * rstd * g[lane + 64] + b[lane + 64]);
    }
    __syncthreads();

    // fragment base addresses (fixed layouts)
    uint32_t a_base[2], h_base[2];
#pragma unroll
    for (int i = 0; i < 2; i++) {
        a_base[i] = cvta_s(&As[warp_m * 32 + i * 16 + lrow][lcol]);
        h_base[i] = cvta_s(&Hs[warp_m * 32 + i * 16 + lrow][lcol]);
    }
    const uint32_t b_base01 = cvta_s(&Bs[warp_n * 24 + lrow][lcol]);       // tiles 0,1 (x4)
    const uint32_t b_base2  = cvta_s(&Bs[warp_n * 24 + 16 + lrow2][lcol2]); // tile 2 (x2)

    float c2[2][3][4];
#pragma unroll
    for (int i = 0; i < 2; i++)
#pragma unroll
        for (int j = 0; j < 3; j++)
#pragma unroll
            for (int e = 0; e < 4; e++) c2[i][j][e] = 0.f;

    for (int hc = 0; hc < 4; hc++) {
        for (int i = tid; i < 1152; i += 256) {
            int row = i / 12, c8 = i - row * 12;
            *reinterpret_cast<uint4*>(&Bs[row][c8 * 4]) =
                *reinterpret_cast<const uint4*>(g_wfc1 + (size_t)(hc * 96 + row) * 96 + c8 * 8);
        }
        __syncthreads();

        float c1[2][3][4];
#pragma unroll
        for (int i = 0; i < 2; i++)
#pragma unroll
            for (int j = 0; j < 3; j++)
#pragma unroll
                for (int e = 0; e < 4; e++) c1[i][j][e] = 0.f;
#pragma unroll
        for (int kk = 0; kk < 48; kk += 8) {
            uint32_t a[2][4], b01[4], b2[2];
#pragma unroll
            for (int i = 0; i < 2; i++) ldsm4(a[i], a_base[i] + kk * 4);
            ldsm4(b01, b_base01 + kk * 4);
            ldsm2(b2, b_base2 + kk * 4);
#pragma unroll
            for (int i = 0; i < 2; i++) {
                uint32_t bb0[2] = { b01[0], b01[2] };
                uint32_t bb1[2] = { b01[1], b01[3] };
                mma_bf16(c1[i][0], a[i], bb0);
                mma_bf16(c1[i][1], a[i], bb1);
                mma_bf16(c1[i][2], a[i], b2);
            }
        }

#pragma unroll
        for (int i = 0; i < 2; i++) {
            int r = warp_m * 32 + i * 16 + grp;
#pragma unroll
            for (int j = 0; j < 3; j++) {
                int cw = warp_n * 12 + j * 4 + qid;
                int n = hc * 96 + cw * 2;
                float b0 = fb1[n], b1 = fb1[n + 1];
                float a0 = c1[i][j][0] + b0, a1 = c1[i][j][1] + b1;
                float a2 = c1[i][j][2] + b0, a3 = c1[i][j][3] + b1;
                a0 = 0.5f * a0 * (1.0f + erff(a0 * 0.70710678118654752f));
                a1 = 0.5f * a1 * (1.0f + erff(a1 * 0.70710678118654752f));
                a2 = 0.5f * a2 * (1.0f + erff(a2 * 0.70710678118654752f));
                a3 = 0.5f * a3 * (1.0f + erff(a3 * 0.70710678118654752f));
                bf162 p0 = __floats2bfloat162_rn(a0, a1);
                bf162 p1 = __floats2bfloat162_rn(a2, a3);
                Hs[r][cw]     = *reinterpret_cast<uint32_t*>(&p0);
                Hs[r + 8][cw] = *reinterpret_cast<uint32_t*>(&p1);
            }
        }
        __syncthreads();

        for (int i = tid; i < 1152; i += 256) {
            int row = i / 12, c8 = i - row * 12;
            *reinterpret_cast<uint4*>(&Bs[row][c8 * 4]) =
                *reinterpret_cast<const uint4*>(g_wfc2 + (size_t)row * 384 + hc * 96 + c8 * 8);
        }
        __syncthreads();

#pragma unroll
        for (int kk = 0; kk < 48; kk += 8) {
            uint32_t a[2][4], b01[4], b2[2];
#pragma unroll
            for (int i = 0; i < 2; i++) ldsm4(a[i], h_base[i] + kk * 4);
            ldsm4(b01, b_base01 + kk * 4);
            ldsm2(b2, b_base2 + kk * 4);
#pragma unroll
            for (int i = 0; i < 2; i++) {
                uint32_t bb0[2] = { b01[0], b01[2] };
                uint32_t bb1[2] = { b01[1], b01[3] };
                mma_bf16(c2[i][0], a[i], bb0);
                mma_bf16(c2[i][1], a[i], bb1);
                mma_bf16(c2[i][2], a[i], b2);
            }
        }
        __syncthreads();
    }

#pragma unroll
    for (int i = 0; i < 2; i++) {
        int r = m0 + warp_m * 32 + i * 16 + grp;
#pragma unroll
        for (int j = 0; j < 3; j++) {
            int n = warp_n * 24 + j * 8 + qid * 2;
            size_t o0 = (size_t)r * CC + n;
            size_t o1 = (size_t)(r + 8) * CC + n;
            float2 x0 = *reinterpret_cast<const float2*>(g_x1 + o0);
            float2 x1v = *reinterpret_cast<const float2*>(g_x1 + o1);
            float b0 = fb2[n], b1 = fb2[n + 1];
            *reinterpret_cast<float2*>(out + o0) =
                make_float2(x0.x + c2[i][j][0] + b0, x0.y + c2[i][j][1] + b1);
            *reinterpret_cast<float2*>(out + o1) =
                make_float2(x1v.x + c2[i][j][2] + b0, x1v.y + c2[i][j][3] + b1);
        }
    }
}

// ---------------------------------------------------------------------------
// Attention: one block per (window, head), 64 threads (R9 proven version)
// ---------------------------------------------------------------------------
__global__ void __launch_bounds__(64) k_attn() {
    int bh = blockIdx.x;
    int win = bh / 3, head = bh - win * 3;
    int widx = win & 255;

    __shared__ __align__(16) float Ks[NTOK * 32];
    __shared__ __align__(16) float Vs[NTOK * 32];
    __shared__ __align__(16) float Ps[NTOK * 51];
    __shared__ __align__(16) float Os[NTOK * 33];

    const size_t base = (size_t)bh * (NTOK * HDD);
    const int tid = threadIdx.x;

    const uint4* qp = reinterpret_cast<const uint4*>(g_qh + base);
    const uint4* kp = reinterpret_cast<const uint4*>(g_kh + base);
    const uint4* vp = reinterpret_cast<const uint4*>(g_vh + base);
    for (int idx = tid; idx < 196; idx += 64) {
        int row = idx >> 2, seg = idx & 3;
        uint4 qv = qp[idx], kv = kp[idx], vv = vp[idx];
        const bf162* q2 = reinterpret_cast<const bf162*>(&qv);
        const bf162* k2 = reinterpret_cast<const bf162*>(&kv);
        const bf162* v2 = reinterpret_cast<const bf162*>(&vv);
        float* qd = Os + row * 33 + seg * 8;
        float* kd = Ks + row * 32 + seg * 8;
        float* vd = Vs + row * 32 + seg * 8;
#pragma unroll
        for (int t = 0; t < 4; t++) {
            float2 f;
            f = __bfloat1622float2(q2[t]); qd[2 * t] = f.x; qd[2 * t + 1] = f.y;
            f = __bfloat1622float2(k2[t]); kd[2 * t] = f.x; kd[2 * t + 1] = f.y;
            f = __bfloat1622float2(v2[t]); vd[2 * t] = f.x; vd[2 * t + 1] = f.y;
        }
    }
    const float* cp = g_comb + (size_t)(widx * 3 + head) * (NTOK * NTOK);
    for (int idx = tid; idx < NTOK * NTOK; idx += 64) {
        int i = idx / NTOK, j = idx - i * NTOK;
        Ps[i * 51 + j] = cp[idx];
    }
    __syncthreads();

    int i = tid;
    if (i < NTOK) {
        float q[32];
#pragma unroll
        for (int d = 0; d < 32; d++) q[d] = Os[i * 33 + d];

        float mx = -1e30f;
        for (int j = 0; j < NTOK; j++) {
            float s = Ps[i * 51 + j];
            const float4* kr = reinterpret_cast<const float4*>(Ks + j * 32);
#pragma unroll
            for (int d4 = 0; d4 < 8; d4++) {
                float4 kv = kr[d4];
                s += q[4 * d4] * kv.x + q[4 * d4 + 1] * kv.y
                   + q[4 * d4 + 2] * kv.z + q[4 * d4 + 3] * kv.w;
            }
            Ps[i * 51 + j] = s;
            mx = fmaxf(mx, s);
        }
        float sum = 0.f;
        for (int j = 0; j < NTOK; j++) {
            float e = __expf(Ps[i * 51 + j] - mx);
            Ps[i * 51 + j] = e;
            sum += e;
        }
        float inv = 1.0f / sum;

        float o[32];
#pragma unroll
        for (int d = 0; d < 32; d++) o[d] = 0.f;
        for (int j = 0; j < NTOK; j++) {
            float p = Ps[i * 51 + j];
            const float4* vr = reinterpret_cast<const float4*>(Vs + j * 32);
#pragma unroll
            for (int d4 = 0; d4 < 8; d4++) {
                float4 vv = vr[d4];
                o[4 * d4]     += p * vv.x;
                o[4 * d4 + 1] += p * vv.y;
                o[4 * d4 + 2] += p * vv.z;
                o[4 * d4 + 3] += p * vv.w;
            }
        }
#pragma unroll
        for (int d = 0; d < 32; d++) Os[i * 33 + d] = o[d] * inv;
    }
    __syncthreads();

    bf16* op = g_atth + (size_t)win * (NTOK * CC) + head * HDD;
    for (int idx = tid; idx < NTOK * 16; idx += 64) {
        int i2 = idx >> 4, dp = idx & 15;
        float a = Os[i2 * 33 + dp * 2], b = Os[i2 * 33 + dp * 2 + 1];
        *reinterpret_cast<bf162*>(op + i2 * CC + dp * 2) = __floats2bfloat162_rn(a, b);
    }
}

// ---------------------------------------------------------------------------
// Launch
// ---------------------------------------------------------------------------
extern "C" void kernel_launch(void* const* d_in, const int* in_sizes, int n_in,
                              void* d_out, int out_size) {
    const float* x         = (const float*)d_in[0];
    const float* attn_mask = (const float*)d_in[1];
    const int*   rel_index = (const int*)  d_in[2];
    const float* n1g       = (const float*)d_in[3];
    const float* n1b       = (const float*)d_in[4];
    const float* qkv_w     = (const float*)d_in[5];
    const float* qkv_b     = (const float*)d_in[6];
    const float* proj_w    = (const float*)d_in[7];
    const float* proj_b    = (const float*)d_in[8];
    const float* tbl       = (const float*)d_in[9];
    const float* n2g       = (const float*)d_in[10];
    const float* n2b       = (const float*)d_in[11];
    const float* fc1_w     = (const float*)d_in[12];
    const float* fc1_b     = (const float*)d_in[13];
    const float* fc2_w     = (const float*)d_in[14];
    const float* fc2_b     = (const float*)d_in[15];
    float* out = (float*)d_out;

    k_prep<<<432, 256>>>(qkv_w, proj_w, fc1_w, fc2_w);
    k_ln1 <<<MTOK / 8, 256>>>(x, n1g, n1b);
    k_comb<<<256 * NHH, 256>>>(attn_mask, rel_index, tbl);
    k_gemm_qkv <<<dim3(3, MTOK / 128), 256>>>(qkv_b);
    k_attn<<<NWIN * NHH, 64>>>();
    k_gemm_proj<<<dim3(1, MTOK / 128), 256>>>(proj_b, x);
    k_mlp<<<MTOK / 64, 256>>>(n2g, n2b, fc1_b, fc2_b, out);
}

// round 13
// speedup vs baseline: 1.2996x; 1.0058x over previous
#include <cuda_runtime.h>
#include <cuda_bf16.h>
#include <math.h>
#include <stdint.h>

// ---------------------------------------------------------------------------
// Problem constants
// ---------------------------------------------------------------------------
#define BB    32
#define HH    112
#define WW2   112
#define CC    96
#define NHH   3
#define WSS   7
#define SHF   3
#define HIDD  384
#define NTOK  49
#define HDD   32
#define NWIN  8192
#define MTOK  401408

typedef __nv_bfloat16 bf16;
typedef __nv_bfloat162 bf162;

// ---------------------------------------------------------------------------
// Scratch (device globals)
// ---------------------------------------------------------------------------
__device__ __align__(16) bf16  g_ln1h[(size_t)MTOK * CC];
__device__ __align__(16) bf16  g_qh[(size_t)NWIN * NHH * NTOK * HDD];
__device__ __align__(16) bf16  g_kh[(size_t)NWIN * NHH * NTOK * HDD];
__device__ __align__(16) bf16  g_vh[(size_t)NWIN * NHH * NTOK * HDD];
__device__ __align__(16) bf16  g_atth[(size_t)MTOK * CC];
__device__ __align__(16) float g_x1[(size_t)MTOK * CC];
__device__ __align__(16) float g_comb[(size_t)256 * NHH * NTOK * NTOK];
__device__ __align__(16) bf16 g_wqkv[288 * 96];
__device__ __align__(16) bf16 g_wproj[96 * 96];
__device__ __align__(16) bf16 g_wfc1[384 * 96];
__device__ __align__(16) bf16 g_wfc2[96 * 384];

__device__ __forceinline__ int rowsrc(int m) {
    int win = m / NTOK, tok = m - win * NTOK;
    int b = win >> 8, widx = win & 255;
    int wh = widx >> 4, ww = widx & 15;
    int r = tok / WSS, c = tok - r * WSS;
    int h = wh * WSS + r + SHF; if (h >= HH) h -= HH;
    int w = ww * WSS + c + SHF; if (w >= WW2) w -= WW2;
    return (b * HH + h) * WW2 + w;
}

// ---------------------------------------------------------------------------
// Weight conversion
// ---------------------------------------------------------------------------
__global__ void __launch_bounds__(256) k_prep(const float* __restrict__ qkvw,
                                              const float* __restrict__ projw,
                                              const float* __restrict__ fc1w,
                                              const float* __restrict__ fc2w) {
    int i = blockIdx.x * 256 + threadIdx.x;
    if (i < 27648)               g_wqkv[i]           = __float2bfloat16(qkvw[i]);
    else if (i < 27648 + 9216)   g_wproj[i - 27648]  = __float2bfloat16(projw[i - 27648]);
    else if (i < 36864 + 36864)  g_wfc1[i - 36864]   = __float2bfloat16(fc1w[i - 36864]);
    else if (i < 110592)         g_wfc2[i - 73728]   = __float2bfloat16(fc2w[i - 73728]);
}

// ---------------------------------------------------------------------------
// LayerNorm1 (warp per token, gathered)
// ---------------------------------------------------------------------------
__global__ void __launch_bounds__(256) k_ln1(const float* __restrict__ x,
                                             const float* __restrict__ g,
                                             const float* __restrict__ b) {
    int m = blockIdx.x * 8 + (threadIdx.x >> 5);
    int lane = threadIdx.x & 31;
    int src = rowsrc(m);
    const float* xr = x + (size_t)src * CC;
    float v0 = xr[lane], v1 = xr[lane + 32], v2 = xr[lane + 64];
    float s = v0 + v1 + v2;
#pragma unroll
    for (int o = 16; o > 0; o >>= 1) s += __shfl_xor_sync(0xffffffffu, s, o);
    float mean = s * (1.0f / 96.0f);
    float d0 = v0 - mean, d1 = v1 - mean, d2 = v2 - mean;
    float sq = d0 * d0 + d1 * d1 + d2 * d2;
#pragma unroll
    for (int o = 16; o > 0; o >>= 1) sq += __shfl_xor_sync(0xffffffffu, sq, o);
    float rstd = rsqrtf(sq * (1.0f / 96.0f) + 1e-5f);
    bf16* orow = g_ln1h + (size_t)m * CC;
    orow[lane]      = (bf16)(d0 * rstd * g[lane]      + b[lane]);
    orow[lane + 32] = (bf16)(d1 * rstd * g[lane + 32] + b[lane + 32]);
    orow[lane + 64] = (bf16)(d2 * rstd * g[lane + 64] + b[lane + 64]);
}

// ---------------------------------------------------------------------------
// Combined additive bias
// ---------------------------------------------------------------------------
__global__ void __launch_bounds__(256) k_comb(const float* __restrict__ mask,
                                              const int* __restrict__ ridx,
                                              const float* __restrict__ table) {
    int wh = blockIdx.x;
    int widx = wh / 3, head = wh - widx * 3;
    const int NN = NTOK * NTOK;
    float* dst = g_comb + (size_t)wh * NN;
    const float* msk = mask + (size_t)widx * NN;
    for (int idx = threadIdx.x; idx < NN; idx += 256)
        dst[idx] = msk[idx] + table[ridx[idx] * NHH + head];
}

// ---------------------------------------------------------------------------
// mma / ldmatrix helpers
// ---------------------------------------------------------------------------
__device__ __forceinline__ void mma_bf16(float* c, const uint32_t* a, const uint32_t* b) {
    asm volatile(
        "mma.sync.aligned.m16n8k16.row.col.f32.bf16.bf16.f32 "
        "{%0,%1,%2,%3}, {%4,%5,%6,%7}, {%8,%9}, {%0,%1,%2,%3};"
        : "+f"(c[0]), "+f"(c[1]), "+f"(c[2]), "+f"(c[3])
        : "r"(a[0]), "r"(a[1]), "r"(a[2]), "r"(a[3]), "r"(b[0]), "r"(b[1]));
}

__device__ __forceinline__ uint32_t cvta_s(const void* p) {
    return (uint32_t)__cvta_generic_to_shared(p);
}
__device__ __forceinline__ void ldsm4(uint32_t* r, uint32_t addr) {
    asm volatile("ldmatrix.sync.aligned.m8n8.x4.shared.b16 {%0,%1,%2,%3}, [%4];"
                 : "=r"(r[0]), "=r"(r[1]), "=r"(r[2]), "=r"(r[3]) : "r"(addr));
}
__device__ __forceinline__ void ldsm2(uint32_t* r, uint32_t addr) {
    asm volatile("ldmatrix.sync.aligned.m8n8.x2.shared.b16 {%0,%1}, [%2];"
                 : "=r"(r[0]), "=r"(r[1]) : "r"(addr));
}

// ---------------------------------------------------------------------------
// BF16 tensor-core GEMM: 128x96 tile, BK=96, 8 warps (4m x 2n), ldmatrix frags
// ---------------------------------------------------------------------------
template <int K, typename Epi>
__device__ __forceinline__ void gemm_body(const bf16* __restrict__ A,
                                          const bf16* __restrict__ W,
                                          Epi epi) {
    constexpr int BK = 96;
    constexpr int KP = 48;
    constexpr int ST = 52;
    __shared__ __align__(16) uint32_t As[128][ST];
    __shared__ __align__(16) uint32_t Bs[96][ST];
    const int tid = threadIdx.x;
    const int wid = tid >> 5, lane = tid & 31;
    const int warp_m = wid >> 1, warp_n = wid & 1;
    const int grp = lane >> 2, qid = lane & 3;
    const int m0 = blockIdx.y * 128;
    const int n0 = blockIdx.x * 96;
    const int lrow = lane & 15;
    const int lcol = (lane >> 4) * 4;

    float c[2][6][4];
#pragma unroll
    for (int i = 0; i < 2; i++)
#pragma unroll
        for (int j = 0; j < 6; j++)
#pragma unroll
            for (int e = 0; e < 4; e++) c[i][j][e] = 0.f;

    for (int k0 = 0; k0 < K; k0 += BK) {
#pragma unroll
        for (int i = 0; i < 6; i++) {
            int idx = tid + i * 256;
            int row = idx / 12, c8 = idx - row * 12;
            uint4 v = *reinterpret_cast<const uint4*>(A + (size_t)(m0 + row) * K + k0 + c8 * 8);
            *reinterpret_cast<uint4*>(&As[row][c8 * 4]) = v;
        }
#pragma unroll
        for (int i = 0; i < 5; i++) {
            int idx = tid + i * 256;
            if (idx < 1152) {
                int row = idx / 12, c8 = idx - row * 12;
                uint4 v = *reinterpret_cast<const uint4*>(W + (size_t)(n0 + row) * K + k0 + c8 * 8);
                *reinterpret_cast<uint4*>(&Bs[row][c8 * 4]) = v;
            }
        }
        __syncthreads();

        uint32_t a_base[2], b_base[3];
#pragma unroll
        for (int i = 0; i < 2; i++)
            a_base[i] = cvta_s(&As[warp_m * 32 + i * 16 + lrow][lcol]);
#pragma unroll
        for (int jp = 0; jp < 3; jp++)
            b_base[jp] = cvta_s(&Bs[warp_n * 48 + jp * 16 + lrow][lcol]);

#pragma unroll
        for (int kk = 0; kk < KP; kk += 8) {
            uint32_t a[2][4], bfr[3][4];
#pragma unroll
            for (int i = 0; i < 2; i++) ldsm4(a[i], a_base[i] + kk * 4);
#pragma unroll
            for (int jp = 0; jp < 3; jp++) ldsm4(bfr[jp], b_base[jp] + kk * 4);
#pragma unroll
            for (int i = 0; i < 2; i++)
#pragma unroll
                for (int j = 0; j < 6; j++) {
                    uint32_t bb[2] = { bfr[j >> 1][j & 1], bfr[j >> 1][2 + (j & 1)] };
                    mma_bf16(c[i][j], a[i], bb);
                }
        }
        __syncthreads();
    }

#pragma unroll
    for (int i = 0; i < 2; i++) {
        int r0 = m0 + warp_m * 32 + i * 16 + grp;
#pragma unroll
        for (int j = 0; j < 6; j++) {
            int cn = n0 + warp_n * 48 + j * 8 + qid * 2;
            epi(r0,     cn, c[i][j][0], c[i][j][1]);
            epi(r0 + 8, cn, c[i][j][2], c[i][j][3]);
        }
    }
}

// ------------------------- epilogues ---------------------------------------
struct QkvEpi {
    const float* bias;
    __device__ void operator()(int m, int n, float v0, float v1) const {
        float a = v0 + bias[n], b = v1 + bias[n + 1];
        int which = n / 96; int rem = n - which * 96;
        int head = rem >> 5; int d = rem & 31;
        int win = m / NTOK; int tok = m - win * NTOK;
        size_t off = ((size_t)(win * 3 + head) * NTOK + tok) * HDD + d;
        if (which == 0) {
            a *= 0.17677669529663689f; b *= 0.17677669529663689f;
            *reinterpret_cast<bf162*>(g_qh + off) = __floats2bfloat162_rn(a, b);
        } else if (which == 1) {
            *reinterpret_cast<bf162*>(g_kh + off) = __floats2bfloat162_rn(a, b);
        } else {
            *reinterpret_cast<bf162*>(g_vh + off) = __floats2bfloat162_rn(a, b);
        }
    }
};

struct ProjEpi {
    const float* x;
    const float* pb;
    __device__ void operator()(int m, int n, float v0, float v1) const {
        int src = rowsrc(m);
        size_t o = (size_t)src * CC + n;
        float2 xv = *reinterpret_cast<const float2*>(x + o);
        float2 r = make_float2(xv.x + v0 + pb[n], xv.y + v1 + pb[n + 1]);
        *reinterpret_cast<float2*>(g_x1 + o) = r;
    }
};

// ------------------------- GEMM wrappers -----------------------------------
__global__ void __launch_bounds__(256) k_gemm_qkv(const float* __restrict__ bias) {
    gemm_body<96>(g_ln1h, g_wqkv, QkvEpi{bias});
}
__global__ void __launch_bounds__(256) k_gemm_proj(const float* __restrict__ pb,
                                                   const float* __restrict__ x) {
    gemm_body<96>(g_atth, g_wproj, ProjEpi{x, pb});
}

// ---------------------------------------------------------------------------
// Fused MLP: LN2 + fc1 + GELU + fc2 + residual.  64 rows/block, 256 threads.
// ---------------------------------------------------------------------------
__global__ void __launch_bounds__(256) k_mlp(const float* __restrict__ g,
                                             const float* __restrict__ b,
                                             const float* __restrict__ fb1,
                                             const float* __restrict__ fb2,
                                             float* __restrict__ out) {
    __shared__ __align__(16) uint32_t As[64][52];
    __shared__ __align__(16) uint32_t Hs[64][52];
    __shared__ __align__(16) uint32_t Bs[96][52];
    const int tid = threadIdx.x;
    const int wid = tid >> 5, lane = tid & 31;
    const int warp_m = wid >> 2;
    const int warp_n = wid & 3;
    const int grp = lane >> 2, qid = lane & 3;
    const int m0 = blockIdx.x * 64;
    const int lrow = lane & 15;
    const int lcol = (lane >> 4) * 4;
    const int lrow2 = lane & 7;
    const int lcol2 = ((lane >> 3) & 1) * 4;

    bf16* asb = reinterpret_cast<bf16*>(As);
    for (int r = wid * 8; r < wid * 8 + 8; r++) {
        const float* xr = g_x1 + (size_t)(m0 + r) * CC;
        float v0 = xr[lane], v1 = xr[lane + 32], v2 = xr[lane + 64];
        float s = v0 + v1 + v2;
#pragma unroll
        for (int o = 16; o > 0; o >>= 1) s += __shfl_xor_sync(0xffffffffu, s, o);
        float mean = s * (1.0f / 96.0f);
        float d0 = v0 - mean, d1 = v1 - mean, d2 = v2 - mean;
        float sq = d0 * d0 + d1 * d1 + d2 * d2;
#pragma unroll
        for (int o = 16; o > 0; o >>= 1) sq += __shfl_xor_sync(0xffffffffu, sq, o);
        float rstd = rsqrtf(sq * (1.0f / 96.0f) + 1e-5f);
        asb[r * 104 + lane]      = (bf16)(d0 * rstd * g[lane]      + b[lane]);
        asb[r * 104 + lane + 32] = (bf16)(d1 * rstd * g[lane + 32] + b[lane + 32]);
        asb[r * 104 + lane + 64] = (bf16)(d2 * rstd * g[lane + 64] + b[lane + 64]);
    }
    __syncthreads();

    uint32_t a_base[2], h_base[2];
#pragma unroll
    for (int i = 0; i < 2; i++) {
        a_base[i] = cvta_s(&As[warp_m * 32 + i * 16 + lrow][lcol]);
        h_base[i] = cvta_s(&Hs[warp_m * 32 + i * 16 + lrow][lcol]);
    }
    const uint32_t b_base01 = cvta_s(&Bs[warp_n * 24 + lrow][lcol]);
    const uint32_t b_base2  = cvta_s(&Bs[warp_n * 24 + 16 + lrow2][lcol2]);

    float c2[2][3][4];
#pragma unroll
    for (int i = 0; i < 2; i++)
#pragma unroll
        for (int j = 0; j < 3; j++)
#pragma unroll
            for (int e = 0; e < 4; e++) c2[i][j][e] = 0.f;

    for (int hc = 0; hc < 4; hc++) {
        for (int i = tid; i < 1152; i += 256) {
            int row = i / 12, c8 = i - row * 12;
            *reinterpret_cast<uint4*>(&Bs[row][c8 * 4]) =
                *reinterpret_cast<const uint4*>(g_wfc1 + (size_t)(hc * 96 + row) * 96 + c8 * 8);
        }
        __syncthreads();

        float c1[2][3][4];
#pragma unroll
        for (int i = 0; i < 2; i++)
#pragma unroll
            for (int j = 0; j < 3; j++)
#pragma unroll
                for (int e = 0; e < 4; e++) c1[i][j][e] = 0.f;
#pragma unroll
        for (int kk = 0; kk < 48; kk += 8) {
            uint32_t a[2][4], b01[4], b2[2];
#pragma unroll
            for (int i = 0; i < 2; i++) ldsm4(a[i], a_base[i] + kk * 4);
            ldsm4(b01, b_base01 + kk * 4);
            ldsm2(b2, b_base2 + kk * 4);
#pragma unroll
            for (int i = 0; i < 2; i++) {
                uint32_t bb0[2] = { b01[0], b01[2] };
                uint32_t bb1[2] = { b01[1], b01[3] };
                mma_bf16(c1[i][0], a[i], bb0);
                mma_bf16(c1[i][1], a[i], bb1);
                mma_bf16(c1[i][2], a[i], b2);
            }
        }

#pragma unroll
        for (int i = 0; i < 2; i++) {
            int r = warp_m * 32 + i * 16 + grp;
#pragma unroll
            for (int j = 0; j < 3; j++) {
                int cw = warp_n * 12 + j * 4 + qid;
                int n = hc * 96 + cw * 2;
                float b0 = fb1[n], b1 = fb1[n + 1];
                float a0 = c1[i][j][0] + b0, a1 = c1[i][j][1] + b1;
                float a2 = c1[i][j][2] + b0, a3 = c1[i][j][3] + b1;
                a0 = 0.5f * a0 * (1.0f + erff(a0 * 0.70710678118654752f));
                a1 = 0.5f * a1 * (1.0f + erff(a1 * 0.70710678118654752f));
                a2 = 0.5f * a2 * (1.0f + erff(a2 * 0.70710678118654752f));
                a3 = 0.5f * a3 * (1.0f + erff(a3 * 0.70710678118654752f));
                bf162 p0 = __floats2bfloat162_rn(a0, a1);
                bf162 p1 = __floats2bfloat162_rn(a2, a3);
                Hs[r][cw]     = *reinterpret_cast<uint32_t*>(&p0);
                Hs[r + 8][cw] = *reinterpret_cast<uint32_t*>(&p1);
            }
        }
        __syncthreads();

        for (int i = tid; i < 1152; i += 256) {
            int row = i / 12, c8 = i - row * 12;
            *reinterpret_cast<uint4*>(&Bs[row][c8 * 4]) =
                *reinterpret_cast<const uint4*>(g_wfc2 + (size_t)row * 384 + hc * 96 + c8 * 8);
        }
        __syncthreads();

#pragma unroll
        for (int kk = 0; kk < 48; kk += 8) {
            uint32_t a[2][4], b01[4], b2[2];
#pragma unroll
            for (int i = 0; i < 2; i++) ldsm4(a[i], h_base[i] + kk * 4);
            ldsm4(b01, b_base01 + kk * 4);
            ldsm2(b2, b_base2 + kk * 4);
#pragma unroll
            for (int i = 0; i < 2; i++) {
                uint32_t bb0[2] = { b01[0], b01[2] };
                uint32_t bb1[2] = { b01[1], b01[3] };
                mma_bf16(c2[i][0], a[i], bb0);
                mma_bf16(c2[i][1], a[i], bb1);
                mma_bf16(c2[i][2], a[i], b2);
            }
        }
        __syncthreads();
    }

#pragma unroll
    for (int i = 0; i < 2; i++) {
        int r = m0 + warp_m * 32 + i * 16 + grp;
#pragma unroll
        for (int j = 0; j < 3; j++) {
            int n = warp_n * 24 + j * 8 + qid * 2;
            size_t o0 = (size_t)r * CC + n;
            size_t o1 = (size_t)(r + 8) * CC + n;
            float2 x0 = *reinterpret_cast<const float2*>(g_x1 + o0);
            float2 x1v = *reinterpret_cast<const float2*>(g_x1 + o1);
            float b0 = fb2[n], b1 = fb2[n + 1];
            *reinterpret_cast<float2*>(out + o0) =
                make_float2(x0.x + c2[i][j][0] + b0, x0.y + c2[i][j][1] + b1);
            *reinterpret_cast<float2*>(out + o1) =
                make_float2(x1v.x + c2[i][j][2] + b0, x1v.y + c2[i][j][3] + b1);
        }
    }
}

// ---------------------------------------------------------------------------
// Attention: one block per (window, head), 64 threads.
// 2-pass: (1) scores -> Ps + max, (2) fused exp + sum + PV accumulate.
// ---------------------------------------------------------------------------
__global__ void __launch_bounds__(64) k_attn() {
    int bh = blockIdx.x;
    int win = bh / 3, head = bh - win * 3;
    int widx = win & 255;

    __shared__ __align__(16) float Ks[NTOK * 32];
    __shared__ __align__(16) float Vs[NTOK * 32];
    __shared__ __align__(16) float Ps[NTOK * 51];
    __shared__ __align__(16) float Os[NTOK * 33];

    const size_t base = (size_t)bh * (NTOK * HDD);
    const int tid = threadIdx.x;

    const uint4* qp = reinterpret_cast<const uint4*>(g_qh + base);
    const uint4* kp = reinterpret_cast<const uint4*>(g_kh + base);
    const uint4* vp = reinterpret_cast<const uint4*>(g_vh + base);
    for (int idx = tid; idx < 196; idx += 64) {
        int row = idx >> 2, seg = idx & 3;
        uint4 qv = qp[idx], kv = kp[idx], vv = vp[idx];
        const bf162* q2 = reinterpret_cast<const bf162*>(&qv);
        const bf162* k2 = reinterpret_cast<const bf162*>(&kv);
        const bf162* v2 = reinterpret_cast<const bf162*>(&vv);
        float* qd = Os + row * 33 + seg * 8;
        float* kd = Ks + row * 32 + seg * 8;
        float* vd = Vs + row * 32 + seg * 8;
#pragma unroll
        for (int t = 0; t < 4; t++) {
            float2 f;
            f = __bfloat1622float2(q2[t]); qd[2 * t] = f.x; qd[2 * t + 1] = f.y;
            f = __bfloat1622float2(k2[t]); kd[2 * t] = f.x; kd[2 * t + 1] = f.y;
            f = __bfloat1622float2(v2[t]); vd[2 * t] = f.x; vd[2 * t + 1] = f.y;
        }
    }
    const float* cp = g_comb + (size_t)(widx * 3 + head) * (NTOK * NTOK);
    for (int idx = tid; idx < NTOK * NTOK; idx += 64) {
        int i = idx / NTOK, j = idx - i * NTOK;
        Ps[i * 51 + j] = cp[idx];
    }
    __syncthreads();

    int i = tid;
    if (i < NTOK) {
        float q[32];
#pragma unroll
        for (int d = 0; d < 32; d++) q[d] = Os[i * 33 + d];

        // pass 1: scores + max
        float mx = -1e30f;
        for (int j = 0; j < NTOK; j++) {
            float s = Ps[i * 51 + j];
            const float4* kr = reinterpret_cast<const float4*>(Ks + j * 32);
#pragma unroll
            for (int d4 = 0; d4 < 8; d4++) {
                float4 kv = kr[d4];
                s += q[4 * d4] * kv.x + q[4 * d4 + 1] * kv.y
                   + q[4 * d4 + 2] * kv.z + q[4 * d4 + 3] * kv.w;
            }
            Ps[i * 51 + j] = s;
            mx = fmaxf(mx, s);
        }

        // pass 2: fused exp + sum + PV accumulate
        float sum = 0.f;
        float o[32];
#pragma unroll
        for (int d = 0; d < 32; d++) o[d] = 0.f;
        for (int j = 0; j < NTOK; j++) {
            float e = __expf(Ps[i * 51 + j] - mx);
            sum += e;
            const float4* vr = reinterpret_cast<const float4*>(Vs + j * 32);
#pragma unroll
            for (int d4 = 0; d4 < 8; d4++) {
                float4 vv = vr[d4];
                o[4 * d4]     += e * vv.x;
                o[4 * d4 + 1] += e * vv.y;
                o[4 * d4 + 2] += e * vv.z;
                o[4 * d4 + 3] += e * vv.w;
            }
        }
        float inv = 1.0f / sum;
#pragma unroll
        for (int d = 0; d < 32; d++) Os[i * 33 + d] = o[d] * inv;
    }
    __syncthreads();

    bf16* op = g_atth + (size_t)win * (NTOK * CC) + head * HDD;
    for (int idx = tid; idx < NTOK * 16; idx += 64) {
        int i2 = idx >> 4, dp = idx & 15;
        float a = Os[i2 * 33 + dp * 2], b = Os[i2 * 33 + dp * 2 + 1];
        *reinterpret_cast<bf162*>(op + i2 * CC + dp * 2) = __floats2bfloat162_rn(a, b);
    }
}

// ---------------------------------------------------------------------------
// Launch
// ---------------------------------------------------------------------------
extern "C" void kernel_launch(void* const* d_in, const int* in_sizes, int n_in,
                              void* d_out, int out_size) {
    const float* x         = (const float*)d_in[0];
    const float* attn_mask = (const float*)d_in[1];
    const int*   rel_index = (const int*)  d_in[2];
    const float* n1g       = (const float*)d_in[3];
    const float* n1b       = (const float*)d_in[4];
    const float* qkv_w     = (const float*)d_in[5];
    const float* qkv_b     = (const float*)d_in[6];
    const float* proj_w    = (const float*)d_in[7];
    const float* proj_b    = (const float*)d_in[8];
    const float* tbl       = (const float*)d_in[9];
    const float* n2g       = (const float*)d_in[10];
    const float* n2b       = (const float*)d_in[11];
    const float* fc1_w     = (const float*)d_in[12];
    const float* fc1_b     = (const float*)d_in[13];
    const float* fc2_w     = (const float*)d_in[14];
    const float* fc2_b     = (const float*)d_in[15];
    float* out = (float*)d_out;

    k_prep<<<432, 256>>>(qkv_w, proj_w, fc1_w, fc2_w);
    k_ln1 <<<MTOK / 8, 256>>>(x, n1g, n1b);
    k_comb<<<256 * NHH, 256>>>(attn_mask, rel_index, tbl);
    k_gemm_qkv <<<dim3(3, MTOK / 128), 256>>>(qkv_b);
    k_attn<<<NWIN * NHH, 64>>>();
    k_gemm_proj<<<dim3(1, MTOK / 128), 256>>>(proj_b, x);
    k_mlp<<<MTOK / 64, 256>>>(n2g, n2b, fc1_b, fc2_b, out);
}

// round 16
// speedup vs baseline: 1.3449x; 1.0349x over previous
#include <cuda_runtime.h>
#include <cuda_bf16.h>
#include <math.h>
#include <stdint.h>

// ---------------------------------------------------------------------------
// Problem constants
// ---------------------------------------------------------------------------
#define BB    32
#define HH    112
#define WW2   112
#define CC    96
#define NHH   3
#define WSS   7
#define SHF   3
#define HIDD  384
#define NTOK  49
#define HDD   32
#define NWIN  8192
#define MTOK  401408

typedef __nv_bfloat16 bf16;
typedef __nv_bfloat162 bf162;

// ---------------------------------------------------------------------------
// Scratch (device globals)
// ---------------------------------------------------------------------------
__device__ __align__(16) bf16  g_ln1h[(size_t)MTOK * CC];
__device__ __align__(16) bf16  g_qh[(size_t)NWIN * NHH * NTOK * HDD];
__device__ __align__(16) bf16  g_kh[(size_t)NWIN * NHH * NTOK * HDD];
__device__ __align__(16) bf16  g_vh[(size_t)NWIN * NHH * NTOK * HDD];
__device__ __align__(16) bf16  g_atth[(size_t)MTOK * CC];
__device__ __align__(16) float g_x1[(size_t)MTOK * CC];
__device__ __align__(16) float g_comb[(size_t)256 * NHH * NTOK * NTOK];
__device__ __align__(16) bf16 g_wqkv[288 * 96];
__device__ __align__(16) bf16 g_wproj[96 * 96];
__device__ __align__(16) bf16 g_wfc1[384 * 96];
__device__ __align__(16) bf16 g_wfc2[96 * 384];

__device__ __forceinline__ int rowsrc(int m) {
    int win = m / NTOK, tok = m - win * NTOK;
    int b = win >> 8, widx = win & 255;
    int wh = widx >> 4, ww = widx & 15;
    int r = tok / WSS, c = tok - r * WSS;
    int h = wh * WSS + r + SHF; if (h >= HH) h -= HH;
    int w = ww * WSS + c + SHF; if (w >= WW2) w -= WW2;
    return (b * HH + h) * WW2 + w;
}

// ---------------------------------------------------------------------------
// Weight conversion
// ---------------------------------------------------------------------------
__global__ void __launch_bounds__(256) k_prep(const float* __restrict__ qkvw,
                                              const float* __restrict__ projw,
                                              const float* __restrict__ fc1w,
                                              const float* __restrict__ fc2w) {
    int i = blockIdx.x * 256 + threadIdx.x;
    if (i < 27648)               g_wqkv[i]           = __float2bfloat16(qkvw[i]);
    else if (i < 27648 + 9216)   g_wproj[i - 27648]  = __float2bfloat16(projw[i - 27648]);
    else if (i < 36864 + 36864)  g_wfc1[i - 36864]   = __float2bfloat16(fc1w[i - 36864]);
    else if (i < 110592)         g_wfc2[i - 73728]   = __float2bfloat16(fc2w[i - 73728]);
}

// ---------------------------------------------------------------------------
// LayerNorm1 (warp per token, gathered)
// ---------------------------------------------------------------------------
__global__ void __launch_bounds__(256) k_ln1(const float* __restrict__ x,
                                             const float* __restrict__ g,
                                             const float* __restrict__ b) {
    int m = blockIdx.x * 8 + (threadIdx.x >> 5);
    int lane = threadIdx.x & 31;
    int src = rowsrc(m);
    const float* xr = x + (size_t)src * CC;
    float v0 = xr[lane], v1 = xr[lane + 32], v2 = xr[lane + 64];
    float s = v0 + v1 + v2;
#pragma unroll
    for (int o = 16; o > 0; o >>= 1) s += __shfl_xor_sync(0xffffffffu, s, o);
    float mean = s * (1.0f / 96.0f);
    float d0 = v0 - mean, d1 = v1 - mean, d2 = v2 - mean;
    float sq = d0 * d0 + d1 * d1 + d2 * d2;
#pragma unroll
    for (int o = 16; o > 0; o >>= 1) sq += __shfl_xor_sync(0xffffffffu, sq, o);
    float rstd = rsqrtf(sq * (1.0f / 96.0f) + 1e-5f);
    bf16* orow = g_ln1h + (size_t)m * CC;
    orow[lane]      = (bf16)(d0 * rstd * g[lane]      + b[lane]);
    orow[lane + 32] = (bf16)(d1 * rstd * g[lane + 32] + b[lane + 32]);
    orow[lane + 64] = (bf16)(d2 * rstd * g[lane + 64] + b[lane + 64]);
}

// ---------------------------------------------------------------------------
// Combined additive bias
// ---------------------------------------------------------------------------
__global__ void __launch_bounds__(256) k_comb(const float* __restrict__ mask,
                                              const int* __restrict__ ridx,
                                              const float* __restrict__ table) {
    int wh = blockIdx.x;
    int widx = wh / 3, head = wh - widx * 3;
    const int NN = NTOK * NTOK;
    float* dst = g_comb + (size_t)wh * NN;
    const float* msk = mask + (size_t)widx * NN;
    for (int idx = threadIdx.x; idx < NN; idx += 256)
        dst[idx] = msk[idx] + table[ridx[idx] * NHH + head];
}

// ---------------------------------------------------------------------------
// mma / ldmatrix / f32x2 helpers
// ---------------------------------------------------------------------------
__device__ __forceinline__ void mma_bf16(float* c, const uint32_t* a, const uint32_t* b) {
    asm volatile(
        "mma.sync.aligned.m16n8k16.row.col.f32.bf16.bf16.f32 "
        "{%0,%1,%2,%3}, {%4,%5,%6,%7}, {%8,%9}, {%0,%1,%2,%3};"
        : "+f"(c[0]), "+f"(c[1]), "+f"(c[2]), "+f"(c[3])
        : "r"(a[0]), "r"(a[1]), "r"(a[2]), "r"(a[3]), "r"(b[0]), "r"(b[1]));
}

__device__ __forceinline__ uint32_t cvta_s(const void* p) {
    return (uint32_t)__cvta_generic_to_shared(p);
}
__device__ __forceinline__ void ldsm4(uint32_t* r, uint32_t addr) {
    asm volatile("ldmatrix.sync.aligned.m8n8.x4.shared.b16 {%0,%1,%2,%3}, [%4];"
                 : "=r"(r[0]), "=r"(r[1]), "=r"(r[2]), "=r"(r[3]) : "r"(addr));
}
__device__ __forceinline__ void ldsm2(uint32_t* r, uint32_t addr) {
    asm volatile("ldmatrix.sync.aligned.m8n8.x2.shared.b16 {%0,%1}, [%2];"
                 : "=r"(r[0]), "=r"(r[1]) : "r"(addr));
}

// packed fp32x2 fma: acc = a*b + acc  (per 32-bit half)
__device__ __forceinline__ void fma2(uint64_t& acc, uint64_t a, uint64_t b) {
    asm("fma.rn.f32x2 %0, %1, %2, %0;" : "+l"(acc) : "l"(a), "l"(b));
}
__device__ __forceinline__ uint64_t pack2(float lo, float hi) {
    uint64_t r;
    asm("mov.b64 %0, {%1, %2};" : "=l"(r) : "f"(lo), "f"(hi));
    return r;
}
__device__ __forceinline__ void unpack2(uint64_t v, float& lo, float& hi) {
    asm("mov.b64 {%0, %1}, %2;" : "=f"(lo), "=f"(hi) : "l"(v));
}

// ---------------------------------------------------------------------------
// BF16 tensor-core GEMM: 128x96 tile, BK=96, 8 warps (4m x 2n), ldmatrix frags
// ---------------------------------------------------------------------------
template <int K, typename Epi>
__device__ __forceinline__ void gemm_body(const bf16* __restrict__ A,
                                          const bf16* __restrict__ W,
                                          Epi epi) {
    constexpr int BK = 96;
    constexpr int KP = 48;
    constexpr int ST = 52;
    __shared__ __align__(16) uint32_t As[128][ST];
    __shared__ __align__(16) uint32_t Bs[96][ST];
    const int tid = threadIdx.x;
    const int wid = tid >> 5, lane = tid & 31;
    const int warp_m = wid >> 1, warp_n = wid & 1;
    const int grp = lane >> 2, qid = lane & 3;
    const int m0 = blockIdx.y * 128;
    const int n0 = blockIdx.x * 96;
    const int lrow = lane & 15;
    const int lcol = (lane >> 4) * 4;

    float c[2][6][4];
#pragma unroll
    for (int i = 0; i < 2; i++)
#pragma unroll
        for (int j = 0; j < 6; j++)
#pragma unroll
            for (int e = 0; e < 4; e++) c[i][j][e] = 0.f;

    for (int k0 = 0; k0 < K; k0 += BK) {
#pragma unroll
        for (int i = 0; i < 6; i++) {
            int idx = tid + i * 256;
            int row = idx / 12, c8 = idx - row * 12;
            uint4 v = *reinterpret_cast<const uint4*>(A + (size_t)(m0 + row) * K + k0 + c8 * 8);
            *reinterpret_cast<uint4*>(&As[row][c8 * 4]) = v;
        }
#pragma unroll
        for (int i = 0; i < 5; i++) {
            int idx = tid + i * 256;
            if (idx < 1152) {
                int row = idx / 12, c8 = idx - row * 12;
                uint4 v = *reinterpret_cast<const uint4*>(W + (size_t)(n0 + row) * K + k0 + c8 * 8);
                *reinterpret_cast<uint4*>(&Bs[row][c8 * 4]) = v;
            }
        }
        __syncthreads();

        uint32_t a_base[2], b_base[3];
#pragma unroll
        for (int i = 0; i < 2; i++)
            a_base[i] = cvta_s(&As[warp_m * 32 + i * 16 + lrow][lcol]);
#pragma unroll
        for (int jp = 0; jp < 3; jp++)
            b_base[jp] = cvta_s(&Bs[warp_n * 48 + jp * 16 + lrow][lcol]);

#pragma unroll
        for (int kk = 0; kk < KP; kk += 8) {
            uint32_t a[2][4], bfr[3][4];
#pragma unroll
            for (int i = 0; i < 2; i++) ldsm4(a[i], a_base[i] + kk * 4);
#pragma unroll
            for (int jp = 0; jp < 3; jp++) ldsm4(bfr[jp], b_base[jp] + kk * 4);
#pragma unroll
            for (int i = 0; i < 2; i++)
#pragma unroll
                for (int j = 0; j < 6; j++) {
                    uint32_t bb[2] = { bfr[j >> 1][j & 1], bfr[j >> 1][2 + (j & 1)] };
                    mma_bf16(c[i][j], a[i], bb);
                }
        }
        __syncthreads();
    }

#pragma unroll
    for (int i = 0; i < 2; i++) {
        int r0 = m0 + warp_m * 32 + i * 16 + grp;
#pragma unroll
        for (int j = 0; j < 6; j++) {
            int cn = n0 + warp_n * 48 + j * 8 + qid * 2;
            epi(r0,     cn, c[i][j][0], c[i][j][1]);
            epi(r0 + 8, cn, c[i][j][2], c[i][j][3]);
        }
    }
}

// ------------------------- epilogues ---------------------------------------
struct QkvEpi {
    const float* bias;
    __device__ void operator()(int m, int n, float v0, float v1) const {
        float a = v0 + bias[n], b = v1 + bias[n + 1];
        int which = n / 96; int rem = n - which * 96;
        int head = rem >> 5; int d = rem & 31;
        int win = m / NTOK; int tok = m - win * NTOK;
        size_t off = ((size_t)(win * 3 + head) * NTOK + tok) * HDD + d;
        if (which == 0) {
            a *= 0.17677669529663689f; b *= 0.17677669529663689f;
            *reinterpret_cast<bf162*>(g_qh + off) = __floats2bfloat162_rn(a, b);
        } else if (which == 1) {
            *reinterpret_cast<bf162*>(g_kh + off) = __floats2bfloat162_rn(a, b);
        } else {
            *reinterpret_cast<bf162*>(g_vh + off) = __floats2bfloat162_rn(a, b);
        }
    }
};

struct ProjEpi {
    const float* x;
    const float* pb;
    __device__ void operator()(int m, int n, float v0, float v1) const {
        int src = rowsrc(m);
        size_t o = (size_t)src * CC + n;
        float2 xv = *reinterpret_cast<const float2*>(x + o);
        float2 r = make_float2(xv.x + v0 + pb[n], xv.y + v1 + pb[n + 1]);
        *reinterpret_cast<float2*>(g_x1 + o) = r;
    }
};

// ------------------------- GEMM wrappers -----------------------------------
__global__ void __launch_bounds__(256) k_gemm_qkv(const float* __restrict__ bias) {
    gemm_body<96>(g_ln1h, g_wqkv, QkvEpi{bias});
}
__global__ void __launch_bounds__(256) k_gemm_proj(const float* __restrict__ pb,
                                                   const float* __restrict__ x) {
    gemm_body<96>(g_atth, g_wproj, ProjEpi{x, pb});
}

// ---------------------------------------------------------------------------
// Fused MLP: LN2 + fc1 + GELU + fc2 + residual.  64 rows/block, 256 threads.
// ---------------------------------------------------------------------------
__global__ void __launch_bounds__(256) k_mlp(const float* __restrict__ g,
                                             const float* __restrict__ b,
                                             const float* __restrict__ fb1,
                                             const float* __restrict__ fb2,
                                             float* __restrict__ out) {
    __shared__ __align__(16) uint32_t As[64][52];
    __shared__ __align__(16) uint32_t Hs[64][52];
    __shared__ __align__(16) uint32_t Bs[96][52];
    const int tid = threadIdx.x;
    const int wid = tid >> 5, lane = tid & 31;
    const int warp_m = wid >> 2;
    const int warp_n = wid & 3;
    const int grp = lane >> 2, qid = lane & 3;
    const int m0 = blockIdx.x * 64;
    const int lrow = lane & 15;
    const int lcol = (lane >> 4) * 4;
    const int lrow2 = lane & 7;
    const int lcol2 = ((lane >> 3) & 1) * 4;

    bf16* asb = reinterpret_cast<bf16*>(As);
    for (int r = wid * 8; r < wid * 8 + 8; r++) {
        const float* xr = g_x1 + (size_t)(m0 + r) * CC;
        float v0 = xr[lane], v1 = xr[lane + 32], v2 = xr[lane + 64];
        float s = v0 + v1 + v2;
#pragma unroll
        for (int o = 16; o > 0; o >>= 1) s += __shfl_xor_sync(0xffffffffu, s, o);
        float mean = s * (1.0f / 96.0f);
        float d0 = v0 - mean, d1 = v1 - mean, d2 = v2 - mean;
        float sq = d0 * d0 + d1 * d1 + d2 * d2;
#pragma unroll
        for (int o = 16; o > 0; o >>= 1) sq += __shfl_xor_sync(0xffffffffu, sq, o);
        float rstd = rsqrtf(sq * (1.0f / 96.0f) + 1e-5f);
        asb[r * 104 + lane]      = (bf16)(d0 * rstd * g[lane]      + b[lane]);
        asb[r * 104 + lane + 32] = (bf16)(d1 * rstd * g[lane + 32] + b[lane + 32]);
        asb[r * 104 + lane + 64] = (bf16)(d2 * rstd * g[lane + 64] + b[lane + 64]);
    }
    __syncthreads();

    uint32_t a_base[2], h_base[2];
#pragma unroll
    for (int i = 0; i < 2; i++) {
        a_base[i] = cvta_s(&As[warp_m * 32 + i * 16 + lrow][lcol]);
        h_base[i] = cvta_s(&Hs[warp_m * 32 + i * 16 + lrow][lcol]);
    }
    const uint32_t b_base01 = cvta_s(&Bs[warp_n * 24 + lrow][lcol]);
    const uint32_t b_base2  = cvta_s(&Bs[warp_n * 24 + 16 + lrow2][lcol2]);

    float c2[2][3][4];
#pragma unroll
    for (int i = 0; i < 2; i++)
#pragma unroll
        for (int j = 0; j < 3; j++)
#pragma unroll
            for (int e = 0; e < 4; e++) c2[i][j][e] = 0.f;

    for (int hc = 0; hc < 4; hc++) {
        for (int i = tid; i < 1152; i += 256) {
            int row = i / 12, c8 = i - row * 12;
            *reinterpret_cast<uint4*>(&Bs[row][c8 * 4]) =
                *reinterpret_cast<const uint4*>(g_wfc1 + (size_t)(hc * 96 + row) * 96 + c8 * 8);
        }
        __syncthreads();

        float c1[2][3][4];
#pragma unroll
        for (int i = 0; i < 2; i++)
#pragma unroll
            for (int j = 0; j < 3; j++)
#pragma unroll
                for (int e = 0; e < 4; e++) c1[i][j][e] = 0.f;
#pragma unroll
        for (int kk = 0; kk < 48; kk += 8) {
            uint32_t a[2][4], b01[4], b2[2];
#pragma unroll
            for (int i = 0; i < 2; i++) ldsm4(a[i], a_base[i] + kk * 4);
            ldsm4(b01, b_base01 + kk * 4);
            ldsm2(b2, b_base2 + kk * 4);
#pragma unroll
            for (int i = 0; i < 2; i++) {
                uint32_t bb0[2] = { b01[0], b01[2] };
                uint32_t bb1[2] = { b01[1], b01[3] };
                mma_bf16(c1[i][0], a[i], bb0);
                mma_bf16(c1[i][1], a[i], bb1);
                mma_bf16(c1[i][2], a[i], b2);
            }
        }

#pragma unroll
        for (int i = 0; i < 2; i++) {
            int r = warp_m * 32 + i * 16 + grp;
#pragma unroll
            for (int j = 0; j < 3; j++) {
                int cw = warp_n * 12 + j * 4 + qid;
                int n = hc * 96 + cw * 2;
                float b0 = fb1[n], b1 = fb1[n + 1];
                float a0 = c1[i][j][0] + b0, a1 = c1[i][j][1] + b1;
                float a2 = c1[i][j][2] + b0, a3 = c1[i][j][3] + b1;
                a0 = 0.5f * a0 * (1.0f + erff(a0 * 0.70710678118654752f));
                a1 = 0.5f * a1 * (1.0f + erff(a1 * 0.70710678118654752f));
                a2 = 0.5f * a2 * (1.0f + erff(a2 * 0.70710678118654752f));
                a3 = 0.5f * a3 * (1.0f + erff(a3 * 0.70710678118654752f));
                bf162 p0 = __floats2bfloat162_rn(a0, a1);
                bf162 p1 = __floats2bfloat162_rn(a2, a3);
                Hs[r][cw]     = *reinterpret_cast<uint32_t*>(&p0);
                Hs[r + 8][cw] = *reinterpret_cast<uint32_t*>(&p1);
            }
        }
        __syncthreads();

        for (int i = tid; i < 1152; i += 256) {
            int row = i / 12, c8 = i - row * 12;
            *reinterpret_cast<uint4*>(&Bs[row][c8 * 4]) =
                *reinterpret_cast<const uint4*>(g_wfc2 + (size_t)row * 384 + hc * 96 + c8 * 8);
        }
        __syncthreads();

#pragma unroll
        for (int kk = 0; kk < 48; kk += 8) {
            uint32_t a[2][4], b01[4], b2[2];
#pragma unroll
            for (int i = 0; i < 2; i++) ldsm4(a[i], h_base[i] + kk * 4);
            ldsm4(b01, b_base01 + kk * 4);
            ldsm2(b2, b_base2 + kk * 4);
#pragma unroll
            for (int i = 0; i < 2; i++) {
                uint32_t bb0[2] = { b01[0], b01[2] };
                uint32_t bb1[2] = { b01[1], b01[3] };
                mma_bf16(c2[i][0], a[i], bb0);
                mma_bf16(c2[i][1], a[i], bb1);
                mma_bf16(c2[i][2], a[i], b2);
            }
        }
        __syncthreads();
    }

#pragma unroll
    for (int i = 0; i < 2; i++) {
        int r = m0 + warp_m * 32 + i * 16 + grp;
#pragma unroll
        for (int j = 0; j < 3; j++) {
            int n = warp_n * 24 + j * 8 + qid * 2;
            size_t o0 = (size_t)r * CC + n;
            size_t o1 = (size_t)(r + 8) * CC + n;
            float2 x0 = *reinterpret_cast<const float2*>(g_x1 + o0);
            float2 x1v = *reinterpret_cast<const float2*>(g_x1 + o1);
            float b0 = fb2[n], b1 = fb2[n + 1];
            *reinterpret_cast<float2*>(out + o0) =
                make_float2(x0.x + c2[i][j][0] + b0, x0.y + c2[i][j][1] + b1);
            *reinterpret_cast<float2*>(out + o1) =
                make_float2(x1v.x + c2[i][j][2] + b0, x1v.y + c2[i][j][3] + b1);
        }
    }
}

// ---------------------------------------------------------------------------
// Attention: one block per (window, head), 64 threads, packed f32x2 FMA.
// ---------------------------------------------------------------------------
__global__ void __launch_bounds__(64) k_attn() {
    int bh = blockIdx.x;
    int win = bh / 3, head = bh - win * 3;
    int widx = win & 255;

    __shared__ __align__(16) float Ks[NTOK * 32];
    __shared__ __align__(16) float Vs[NTOK * 32];
    __shared__ __align__(16) float Ps[NTOK * 51];
    __shared__ __align__(16) float Os[NTOK * 34];   // even stride: u64-aligned rows

    const size_t base = (size_t)bh * (NTOK * HDD);
    const int tid = threadIdx.x;

    const uint4* qp = reinterpret_cast<const uint4*>(g_qh + base);
    const uint4* kp = reinterpret_cast<const uint4*>(g_kh + base);
    const uint4* vp = reinterpret_cast<const uint4*>(g_vh + base);
    for (int idx = tid; idx < 196; idx += 64) {
        int row = idx >> 2, seg = idx & 3;
        uint4 qv = qp[idx], kv = kp[idx], vv = vp[idx];
        const bf162* q2 = reinterpret_cast<const bf162*>(&qv);
        const bf162* k2 = reinterpret_cast<const bf162*>(&kv);
        const bf162* v2 = reinterpret_cast<const bf162*>(&vv);
        float* qd = Os + row * 34 + seg * 8;
        float* kd = Ks + row * 32 + seg * 8;
        float* vd = Vs + row * 32 + seg * 8;
#pragma unroll
        for (int t = 0; t < 4; t++) {
            float2 f;
            f = __bfloat1622float2(q2[t]); qd[2 * t] = f.x; qd[2 * t + 1] = f.y;
            f = __bfloat1622float2(k2[t]); kd[2 * t] = f.x; kd[2 * t + 1] = f.y;
            f = __bfloat1622float2(v2[t]); vd[2 * t] = f.x; vd[2 * t + 1] = f.y;
        }
    }
    const float* cp = g_comb + (size_t)(widx * 3 + head) * (NTOK * NTOK);
    for (int idx = tid; idx < NTOK * NTOK; idx += 64) {
        int i = idx / NTOK, j = idx - i * NTOK;
        Ps[i * 51 + j] = cp[idx];
    }
    __syncthreads();

    int i = tid;
    if (i < NTOK) {
        // Q row as 16 packed f32x2
        uint64_t q2r[16];
        const uint64_t* qrow = reinterpret_cast<const uint64_t*>(Os + i * 34);
#pragma unroll
        for (int p = 0; p < 16; p++) q2r[p] = qrow[p];

        // pass 1: scores (packed dot) + max
        float mx = -1e30f;
        for (int j = 0; j < NTOK; j++) {
            uint64_t s2 = 0;                            // (0.0f, 0.0f)
            const uint64_t* kr = reinterpret_cast<const uint64_t*>(Ks + j * 32);
#pragma unroll
            for (int p = 0; p < 16; p++) fma2(s2, q2r[p], kr[p]);
            float lo, hi; unpack2(s2, lo, hi);
            float s = Ps[i * 51 + j] + lo + hi;
            Ps[i * 51 + j] = s;
            mx = fmaxf(mx, s);
        }

        // pass 2: fused exp + sum + packed PV accumulate
        float sum = 0.f;
        uint64_t o2[16];
#pragma unroll
        for (int p = 0; p < 16; p++) o2[p] = 0;
        for (int j = 0; j < NTOK; j++) {
            float e = __expf(Ps[i * 51 + j] - mx);
            sum += e;
            uint64_t e2 = pack2(e, e);
            const uint64_t* vr = reinterpret_cast<const uint64_t*>(Vs + j * 32);
#pragma unroll
            for (int p = 0; p < 16; p++) fma2(o2[p], e2, vr[p]);
        }
        float inv = 1.0f / sum;
#pragma unroll
        for (int p = 0; p < 16; p++) {
            float lo, hi; unpack2(o2[p], lo, hi);
            Os[i * 34 + 2 * p]     = lo * inv;
            Os[i * 34 + 2 * p + 1] = hi * inv;
        }
    }
    __syncthreads();

    bf16* op = g_atth + (size_t)win * (NTOK * CC) + head * HDD;
    for (int idx = tid; idx < NTOK * 16; idx += 64) {
        int i2 = idx >> 4, dp = idx & 15;
        float a = Os[i2 * 34 + dp * 2], b = Os[i2 * 34 + dp * 2 + 1];
        *reinterpret_cast<bf162*>(op + i2 * CC + dp * 2) = __floats2bfloat162_rn(a, b);
    }
}

// ---------------------------------------------------------------------------
// Launch
// ---------------------------------------------------------------------------
extern "C" void kernel_launch(void* const* d_in, const int* in_sizes, int n_in,
                              void* d_out, int out_size) {
    const float* x         = (const float*)d_in[0];
    const float* attn_mask = (const float*)d_in[1];
    const int*   rel_index = (const int*)  d_in[2];
    const float* n1g       = (const float*)d_in[3];
    const float* n1b       = (const float*)d_in[4];
    const float* qkv_w     = (const float*)d_in[5];
    const float* qkv_b     = (const float*)d_in[6];
    const float* proj_w    = (const float*)d_in[7];
    const float* proj_b    = (const float*)d_in[8];
    const float* tbl       = (const float*)d_in[9];
    const float* n2g       = (const float*)d_in[10];
    const float* n2b       = (const float*)d_in[11];
    const float* fc1_w     = (const float*)d_in[12];
    const float* fc1_b     = (const float*)d_in[13];
    const float* fc2_w     = (const float*)d_in[14];
    const float* fc2_b     = (const float*)d_in[15];
    float* out = (float*)d_out;

    k_prep<<<432, 256>>>(qkv_w, proj_w, fc1_w, fc2_w);
    k_ln1 <<<MTOK / 8, 256>>>(x, n1g, n1b);
    k_comb<<<256 * NHH, 256>>>(attn_mask, rel_index, tbl);
    k_gemm_qkv <<<dim3(3, MTOK / 128), 256>>>(qkv_b);
    k_attn<<<NWIN * NHH, 64>>>();
    k_gemm_proj<<<dim3(1, MTOK / 128), 256>>>(proj_b, x);
    k_mlp<<<MTOK / 64, 256>>>(n2g, n2b, fc1_b, fc2_b, out);
}

// round 17
// speedup vs baseline: 1.4102x; 1.0486x over previous
#include <cuda_runtime.h>
#include <cuda_bf16.h>
#include <math.h>
#include <stdint.h>

// ---------------------------------------------------------------------------
// Problem constants
// ---------------------------------------------------------------------------
#define BB    32
#define HH    112
#define WW2   112
#define CC    96
#define NHH   3
#define WSS   7
#define SHF   3
#define HIDD  384
#define NTOK  49
#define HDD   32
#define NWIN  8192
#define MTOK  401408

typedef __nv_bfloat16 bf16;
typedef __nv_bfloat162 bf162;

// ---------------------------------------------------------------------------
// Scratch (device globals)
// ---------------------------------------------------------------------------
__device__ __align__(16) bf16  g_ln1h[(size_t)MTOK * CC];
__device__ __align__(16) bf16  g_qh[(size_t)NWIN * NHH * NTOK * HDD];
__device__ __align__(16) bf16  g_kh[(size_t)NWIN * NHH * NTOK * HDD];
__device__ __align__(16) bf16  g_vh[(size_t)NWIN * NHH * NTOK * HDD];
__device__ __align__(16) bf16  g_atth[(size_t)MTOK * CC];
__device__ __align__(16) float g_x1[(size_t)MTOK * CC];
__device__ __align__(16) float g_comb[(size_t)256 * NHH * NTOK * NTOK];
__device__ __align__(16) bf16 g_wqkv[288 * 96];
__device__ __align__(16) bf16 g_wproj[96 * 96];
__device__ __align__(16) bf16 g_wfc1[384 * 96];
__device__ __align__(16) bf16 g_wfc2[96 * 384];

__device__ __forceinline__ int rowsrc(int m) {
    int win = m / NTOK, tok = m - win * NTOK;
    int b = win >> 8, widx = win & 255;
    int wh = widx >> 4, ww = widx & 15;
    int r = tok / WSS, c = tok - r * WSS;
    int h = wh * WSS + r + SHF; if (h >= HH) h -= HH;
    int w = ww * WSS + c + SHF; if (w >= WW2) w -= WW2;
    return (b * HH + h) * WW2 + w;
}

// ---------------------------------------------------------------------------
// Weight conversion
// ---------------------------------------------------------------------------
__global__ void __launch_bounds__(256) k_prep(const float* __restrict__ qkvw,
                                              const float* __restrict__ projw,
                                              const float* __restrict__ fc1w,
                                              const float* __restrict__ fc2w) {
    int i = blockIdx.x * 256 + threadIdx.x;
    if (i < 27648)               g_wqkv[i]           = __float2bfloat16(qkvw[i]);
    else if (i < 27648 + 9216)   g_wproj[i - 27648]  = __float2bfloat16(projw[i - 27648]);
    else if (i < 36864 + 36864)  g_wfc1[i - 36864]   = __float2bfloat16(fc1w[i - 36864]);
    else if (i < 110592)         g_wfc2[i - 73728]   = __float2bfloat16(fc2w[i - 73728]);
}

// ---------------------------------------------------------------------------
// LayerNorm1 (warp per token, gathered)
// ---------------------------------------------------------------------------
__global__ void __launch_bounds__(256) k_ln1(const float* __restrict__ x,
                                             const float* __restrict__ g,
                                             const float* __restrict__ b) {
    int m = blockIdx.x * 8 + (threadIdx.x >> 5);
    int lane = threadIdx.x & 31;
    int src = rowsrc(m);
    const float* xr = x + (size_t)src * CC;
    float v0 = xr[lane], v1 = xr[lane + 32], v2 = xr[lane + 64];
    float s = v0 + v1 + v2;
#pragma unroll
    for (int o = 16; o > 0; o >>= 1) s += __shfl_xor_sync(0xffffffffu, s, o);
    float mean = s * (1.0f / 96.0f);
    float d0 = v0 - mean, d1 = v1 - mean, d2 = v2 - mean;
    float sq = d0 * d0 + d1 * d1 + d2 * d2;
#pragma unroll
    for (int o = 16; o > 0; o >>= 1) sq += __shfl_xor_sync(0xffffffffu, sq, o);
    float rstd = rsqrtf(sq * (1.0f / 96.0f) + 1e-5f);
    bf16* orow = g_ln1h + (size_t)m * CC;
    orow[lane]      = (bf16)(d0 * rstd * g[lane]      + b[lane]);
    orow[lane + 32] = (bf16)(d1 * rstd * g[lane + 32] + b[lane + 32]);
    orow[lane + 64] = (bf16)(d2 * rstd * g[lane + 64] + b[lane + 64]);
}

// ---------------------------------------------------------------------------
// Combined additive bias
// ---------------------------------------------------------------------------
__global__ void __launch_bounds__(256) k_comb(const float* __restrict__ mask,
                                              const int* __restrict__ ridx,
                                              const float* __restrict__ table) {
    int wh = blockIdx.x;
    int widx = wh / 3, head = wh - widx * 3;
    const int NN = NTOK * NTOK;
    float* dst = g_comb + (size_t)wh * NN;
    const float* msk = mask + (size_t)widx * NN;
    for (int idx = threadIdx.x; idx < NN; idx += 256)
        dst[idx] = msk[idx] + table[ridx[idx] * NHH + head];
}

// ---------------------------------------------------------------------------
// mma / ldmatrix / f32x2 helpers
// ---------------------------------------------------------------------------
__device__ __forceinline__ void mma_bf16(float* c, const uint32_t* a, const uint32_t* b) {
    asm volatile(
        "mma.sync.aligned.m16n8k16.row.col.f32.bf16.bf16.f32 "
        "{%0,%1,%2,%3}, {%4,%5,%6,%7}, {%8,%9}, {%0,%1,%2,%3};"
        : "+f"(c[0]), "+f"(c[1]), "+f"(c[2]), "+f"(c[3])
        : "r"(a[0]), "r"(a[1]), "r"(a[2]), "r"(a[3]), "r"(b[0]), "r"(b[1]));
}

__device__ __forceinline__ uint32_t cvta_s(const void* p) {
    return (uint32_t)__cvta_generic_to_shared(p);
}
__device__ __forceinline__ void ldsm4(uint32_t* r, uint32_t addr) {
    asm volatile("ldmatrix.sync.aligned.m8n8.x4.shared.b16 {%0,%1,%2,%3}, [%4];"
                 : "=r"(r[0]), "=r"(r[1]), "=r"(r[2]), "=r"(r[3]) : "r"(addr));
}
__device__ __forceinline__ void ldsm2(uint32_t* r, uint32_t addr) {
    asm volatile("ldmatrix.sync.aligned.m8n8.x2.shared.b16 {%0,%1}, [%2];"
                 : "=r"(r[0]), "=r"(r[1]) : "r"(addr));
}

// packed fp32x2 fma: acc = a*b + acc  (per 32-bit half)
__device__ __forceinline__ void fma2(uint64_t& acc, uint64_t a, uint64_t b) {
    asm("fma.rn.f32x2 %0, %1, %2, %0;" : "+l"(acc) : "l"(a), "l"(b));
}
__device__ __forceinline__ uint64_t pack2(float lo, float hi) {
    uint64_t r;
    asm("mov.b64 %0, {%1, %2};" : "=l"(r) : "f"(lo), "f"(hi));
    return r;
}
__device__ __forceinline__ uint64_t pack2u(uint32_t lo, uint32_t hi) {
    uint64_t r;
    asm("mov.b64 %0, {%1, %2};" : "=l"(r) : "r"(lo), "r"(hi));
    return r;
}
__device__ __forceinline__ void unpack2(uint64_t v, float& lo, float& hi) {
    asm("mov.b64 {%0, %1}, %2;" : "=f"(lo), "=f"(hi) : "l"(v));
}

// ---------------------------------------------------------------------------
// BF16 tensor-core GEMM: 128x96 tile, BK=96, 8 warps (4m x 2n), ldmatrix frags
// ---------------------------------------------------------------------------
template <int K, typename Epi>
__device__ __forceinline__ void gemm_body(const bf16* __restrict__ A,
                                          const bf16* __restrict__ W,
                                          Epi epi) {
    constexpr int BK = 96;
    constexpr int KP = 48;
    constexpr int ST = 52;
    __shared__ __align__(16) uint32_t As[128][ST];
    __shared__ __align__(16) uint32_t Bs[96][ST];
    const int tid = threadIdx.x;
    const int wid = tid >> 5, lane = tid & 31;
    const int warp_m = wid >> 1, warp_n = wid & 1;
    const int grp = lane >> 2, qid = lane & 3;
    const int m0 = blockIdx.y * 128;
    const int n0 = blockIdx.x * 96;
    const int lrow = lane & 15;
    const int lcol = (lane >> 4) * 4;

    float c[2][6][4];
#pragma unroll
    for (int i = 0; i < 2; i++)
#pragma unroll
        for (int j = 0; j < 6; j++)
#pragma unroll
            for (int e = 0; e < 4; e++) c[i][j][e] = 0.f;

    for (int k0 = 0; k0 < K; k0 += BK) {
#pragma unroll
        for (int i = 0; i < 6; i++) {
            int idx = tid + i * 256;
            int row = idx / 12, c8 = idx - row * 12;
            uint4 v = *reinterpret_cast<const uint4*>(A + (size_t)(m0 + row) * K + k0 + c8 * 8);
            *reinterpret_cast<uint4*>(&As[row][c8 * 4]) = v;
        }
#pragma unroll
        for (int i = 0; i < 5; i++) {
            int idx = tid + i * 256;
            if (idx < 1152) {
                int row = idx / 12, c8 = idx - row * 12;
                uint4 v = *reinterpret_cast<const uint4*>(W + (size_t)(n0 + row) * K + k0 + c8 * 8);
                *reinterpret_cast<uint4*>(&Bs[row][c8 * 4]) = v;
            }
        }
        __syncthreads();

        uint32_t a_base[2], b_base[3];
#pragma unroll
        for (int i = 0; i < 2; i++)
            a_base[i] = cvta_s(&As[warp_m * 32 + i * 16 + lrow][lcol]);
#pragma unroll
        for (int jp = 0; jp < 3; jp++)
            b_base[jp] = cvta_s(&Bs[warp_n * 48 + jp * 16 + lrow][lcol]);

#pragma unroll
        for (int kk = 0; kk < KP; kk += 8) {
            uint32_t a[2][4], bfr[3][4];
#pragma unroll
            for (int i = 0; i < 2; i++) ldsm4(a[i], a_base[i] + kk * 4);
#pragma unroll
            for (int jp = 0; jp < 3; jp++) ldsm4(bfr[jp], b_base[jp] + kk * 4);
#pragma unroll
            for (int i = 0; i < 2; i++)
#pragma unroll
                for (int j = 0; j < 6; j++) {
                    uint32_t bb[2] = { bfr[j >> 1][j & 1], bfr[j >> 1][2 + (j & 1)] };
                    mma_bf16(c[i][j], a[i], bb);
                }
        }
        __syncthreads();
    }

#pragma unroll
    for (int i = 0; i < 2; i++) {
        int r0 = m0 + warp_m * 32 + i * 16 + grp;
#pragma unroll
        for (int j = 0; j < 6; j++) {
            int cn = n0 + warp_n * 48 + j * 8 + qid * 2;
            epi(r0,     cn, c[i][j][0], c[i][j][1]);
            epi(r0 + 8, cn, c[i][j][2], c[i][j][3]);
        }
    }
}

// ------------------------- epilogues ---------------------------------------
struct QkvEpi {
    const float* bias;
    __device__ void operator()(int m, int n, float v0, float v1) const {
        float a = v0 + bias[n], b = v1 + bias[n + 1];
        int which = n / 96; int rem = n - which * 96;
        int head = rem >> 5; int d = rem & 31;
        int win = m / NTOK; int tok = m - win * NTOK;
        size_t off = ((size_t)(win * 3 + head) * NTOK + tok) * HDD + d;
        if (which == 0) {
            a *= 0.17677669529663689f; b *= 0.17677669529663689f;
            *reinterpret_cast<bf162*>(g_qh + off) = __floats2bfloat162_rn(a, b);
        } else if (which == 1) {
            *reinterpret_cast<bf162*>(g_kh + off) = __floats2bfloat162_rn(a, b);
        } else {
            *reinterpret_cast<bf162*>(g_vh + off) = __floats2bfloat162_rn(a, b);
        }
    }
};

struct ProjEpi {
    const float* x;
    const float* pb;
    __device__ void operator()(int m, int n, float v0, float v1) const {
        int src = rowsrc(m);
        size_t o = (size_t)src * CC + n;
        float2 xv = *reinterpret_cast<const float2*>(x + o);
        float2 r = make_float2(xv.x + v0 + pb[n], xv.y + v1 + pb[n + 1]);
        *reinterpret_cast<float2*>(g_x1 + o) = r;
    }
};

// ------------------------- GEMM wrappers -----------------------------------
__global__ void __launch_bounds__(256) k_gemm_qkv(const float* __restrict__ bias) {
    gemm_body<96>(g_ln1h, g_wqkv, QkvEpi{bias});
}
__global__ void __launch_bounds__(256) k_gemm_proj(const float* __restrict__ pb,
                                                   const float* __restrict__ x) {
    gemm_body<96>(g_atth, g_wproj, ProjEpi{x, pb});
}

// ---------------------------------------------------------------------------
// Fused MLP: LN2 + fc1 + GELU + fc2 + residual.  64 rows/block, 256 threads.
// fc2 weight chunks prefetched into registers during GEMM1.
// ---------------------------------------------------------------------------
__global__ void __launch_bounds__(256) k_mlp(const float* __restrict__ g,
                                             const float* __restrict__ b,
                                             const float* __restrict__ fb1,
                                             const float* __restrict__ fb2,
                                             float* __restrict__ out) {
    __shared__ __align__(16) uint32_t As[64][52];
    __shared__ __align__(16) uint32_t Hs[64][52];
    __shared__ __align__(16) uint32_t Bs[96][52];
    const int tid = threadIdx.x;
    const int wid = tid >> 5, lane = tid & 31;
    const int warp_m = wid >> 2;
    const int warp_n = wid & 3;
    const int grp = lane >> 2, qid = lane & 3;
    const int m0 = blockIdx.x * 64;
    const int lrow = lane & 15;
    const int lcol = (lane >> 4) * 4;
    const int lrow2 = lane & 7;
    const int lcol2 = ((lane >> 3) & 1) * 4;

    bf16* asb = reinterpret_cast<bf16*>(As);
    for (int r = wid * 8; r < wid * 8 + 8; r++) {
        const float* xr = g_x1 + (size_t)(m0 + r) * CC;
        float v0 = xr[lane], v1 = xr[lane + 32], v2 = xr[lane + 64];
        float s = v0 + v1 + v2;
#pragma unroll
        for (int o = 16; o > 0; o >>= 1) s += __shfl_xor_sync(0xffffffffu, s, o);
        float mean = s * (1.0f / 96.0f);
        float d0 = v0 - mean, d1 = v1 - mean, d2 = v2 - mean;
        float sq = d0 * d0 + d1 * d1 + d2 * d2;
#pragma unroll
        for (int o = 16; o > 0; o >>= 1) sq += __shfl_xor_sync(0xffffffffu, sq, o);
        float rstd = rsqrtf(sq * (1.0f / 96.0f) + 1e-5f);
        asb[r * 104 + lane]      = (bf16)(d0 * rstd * g[lane]      + b[lane]);
        asb[r * 104 + lane + 32] = (bf16)(d1 * rstd * g[lane + 32] + b[lane + 32]);
        asb[r * 104 + lane + 64] = (bf16)(d2 * rstd * g[lane + 64] + b[lane + 64]);
    }
    __syncthreads();

    uint32_t a_base[2], h_base[2];
#pragma unroll
    for (int i = 0; i < 2; i++) {
        a_base[i] = cvta_s(&As[warp_m * 32 + i * 16 + lrow][lcol]);
        h_base[i] = cvta_s(&Hs[warp_m * 32 + i * 16 + lrow][lcol]);
    }
    const uint32_t b_base01 = cvta_s(&Bs[warp_n * 24 + lrow][lcol]);
    const uint32_t b_base2  = cvta_s(&Bs[warp_n * 24 + 16 + lrow2][lcol2]);

    // thread's Bs-loader slots (4 or 5 of 1152)
    int ld_row[5], ld_c8[5], ld_cnt = 0;
#pragma unroll
    for (int i = 0; i < 5; i++) {
        int idx = tid + i * 256;
        if (idx < 1152) { ld_row[ld_cnt] = idx / 12; ld_c8[ld_cnt] = idx - (idx / 12) * 12; ld_cnt++; }
    }

    float c2[2][3][4];
#pragma unroll
    for (int i = 0; i < 2; i++)
#pragma unroll
        for (int j = 0; j < 3; j++)
#pragma unroll
            for (int e = 0; e < 4; e++) c2[i][j][e] = 0.f;

    for (int hc = 0; hc < 4; hc++) {
        // load fc1 chunk into Bs
#pragma unroll
        for (int t = 0; t < 5; t++)
            if (t < ld_cnt)
                *reinterpret_cast<uint4*>(&Bs[ld_row[t]][ld_c8[t] * 4]) =
                    *reinterpret_cast<const uint4*>(g_wfc1 + (size_t)(hc * 96 + ld_row[t]) * 96 + ld_c8[t] * 8);
        __syncthreads();

        // prefetch fc2 chunk into registers (hidden behind GEMM1)
        uint4 r_w2[5];
#pragma unroll
        for (int t = 0; t < 5; t++)
            if (t < ld_cnt)
                r_w2[t] = *reinterpret_cast<const uint4*>(g_wfc2 + (size_t)ld_row[t] * 384 + hc * 96 + ld_c8[t] * 8);

        float c1[2][3][4];
#pragma unroll
        for (int i = 0; i < 2; i++)
#pragma unroll
            for (int j = 0; j < 3; j++)
#pragma unroll
                for (int e = 0; e < 4; e++) c1[i][j][e] = 0.f;
#pragma unroll
        for (int kk = 0; kk < 48; kk += 8) {
            uint32_t a[2][4], b01[4], b2[2];
#pragma unroll
            for (int i = 0; i < 2; i++) ldsm4(a[i], a_base[i] + kk * 4);
            ldsm4(b01, b_base01 + kk * 4);
            ldsm2(b2, b_base2 + kk * 4);
#pragma unroll
            for (int i = 0; i < 2; i++) {
                uint32_t bb0[2] = { b01[0], b01[2] };
                uint32_t bb1[2] = { b01[1], b01[3] };
                mma_bf16(c1[i][0], a[i], bb0);
                mma_bf16(c1[i][1], a[i], bb1);
                mma_bf16(c1[i][2], a[i], b2);
            }
        }

#pragma unroll
        for (int i = 0; i < 2; i++) {
            int r = warp_m * 32 + i * 16 + grp;
#pragma unroll
            for (int j = 0; j < 3; j++) {
                int cw = warp_n * 12 + j * 4 + qid;
                int n = hc * 96 + cw * 2;
                float b0 = fb1[n], b1 = fb1[n + 1];
                float a0 = c1[i][j][0] + b0, a1 = c1[i][j][1] + b1;
                float a2 = c1[i][j][2] + b0, a3 = c1[i][j][3] + b1;
                a0 = 0.5f * a0 * (1.0f + erff(a0 * 0.70710678118654752f));
                a1 = 0.5f * a1 * (1.0f + erff(a1 * 0.70710678118654752f));
                a2 = 0.5f * a2 * (1.0f + erff(a2 * 0.70710678118654752f));
                a3 = 0.5f * a3 * (1.0f + erff(a3 * 0.70710678118654752f));
                bf162 p0 = __floats2bfloat162_rn(a0, a1);
                bf162 p1 = __floats2bfloat162_rn(a2, a3);
                Hs[r][cw]     = *reinterpret_cast<uint32_t*>(&p0);
                Hs[r + 8][cw] = *reinterpret_cast<uint32_t*>(&p1);
            }
        }
        __syncthreads();

        // store prefetched fc2 chunk into Bs
#pragma unroll
        for (int t = 0; t < 5; t++)
            if (t < ld_cnt)
                *reinterpret_cast<uint4*>(&Bs[ld_row[t]][ld_c8[t] * 4]) = r_w2[t];
        __syncthreads();

#pragma unroll
        for (int kk = 0; kk < 48; kk += 8) {
            uint32_t a[2][4], b01[4], b2[2];
#pragma unroll
            for (int i = 0; i < 2; i++) ldsm4(a[i], h_base[i] + kk * 4);
            ldsm4(b01, b_base01 + kk * 4);
            ldsm2(b2, b_base2 + kk * 4);
#pragma unroll
            for (int i = 0; i < 2; i++) {
                uint32_t bb0[2] = { b01[0], b01[2] };
                uint32_t bb1[2] = { b01[1], b01[3] };
                mma_bf16(c2[i][0], a[i], bb0);
                mma_bf16(c2[i][1], a[i], bb1);
                mma_bf16(c2[i][2], a[i], b2);
            }
        }
        __syncthreads();
    }

#pragma unroll
    for (int i = 0; i < 2; i++) {
        int r = m0 + warp_m * 32 + i * 16 + grp;
#pragma unroll
        for (int j = 0; j < 3; j++) {
            int n = warp_n * 24 + j * 8 + qid * 2;
            size_t o0 = (size_t)r * CC + n;
            size_t o1 = (size_t)(r + 8) * CC + n;
            float2 x0 = *reinterpret_cast<const float2*>(g_x1 + o0);
            float2 x1v = *reinterpret_cast<const float2*>(g_x1 + o1);
            float b0 = fb2[n], b1 = fb2[n + 1];
            *reinterpret_cast<float2*>(out + o0) =
                make_float2(x0.x + c2[i][j][0] + b0, x0.y + c2[i][j][1] + b1);
            *reinterpret_cast<float2*>(out + o1) =
                make_float2(x1v.x + c2[i][j][2] + b0, x1v.y + c2[i][j][3] + b1);
        }
    }
}

// ---------------------------------------------------------------------------
// Attention: one block per (window, head), 64 threads, f32x2 FMA + LDS.128
// ---------------------------------------------------------------------------
__global__ void __launch_bounds__(64) k_attn() {
    int bh = blockIdx.x;
    int win = bh / 3, head = bh - win * 3;
    int widx = win & 255;

    __shared__ __align__(16) float Ks[NTOK * 32];
    __shared__ __align__(16) float Vs[NTOK * 32];
    __shared__ __align__(16) float Ps[NTOK * 51];
    __shared__ __align__(16) float Os[NTOK * 34];   // even stride: u64-aligned rows

    const size_t base = (size_t)bh * (NTOK * HDD);
    const int tid = threadIdx.x;

    const uint4* qp = reinterpret_cast<const uint4*>(g_qh + base);
    const uint4* kp = reinterpret_cast<const uint4*>(g_kh + base);
    const uint4* vp = reinterpret_cast<const uint4*>(g_vh + base);
    for (int idx = tid; idx < 196; idx += 64) {
        int row = idx >> 2, seg = idx & 3;
        uint4 qv = qp[idx], kv = kp[idx], vv = vp[idx];
        const bf162* q2 = reinterpret_cast<const bf162*>(&qv);
        const bf162* k2 = reinterpret_cast<const bf162*>(&kv);
        const bf162* v2 = reinterpret_cast<const bf162*>(&vv);
        float* qd = Os + row * 34 + seg * 8;
        float* kd = Ks + row * 32 + seg * 8;
        float* vd = Vs + row * 32 + seg * 8;
#pragma unroll
        for (int t = 0; t < 4; t++) {
            float2 f;
            f = __bfloat1622float2(q2[t]); qd[2 * t] = f.x; qd[2 * t + 1] = f.y;
            f = __bfloat1622float2(k2[t]); kd[2 * t] = f.x; kd[2 * t + 1] = f.y;
            f = __bfloat1622float2(v2[t]); vd[2 * t] = f.x; vd[2 * t + 1] = f.y;
        }
    }
    const float* cp = g_comb + (size_t)(widx * 3 + head) * (NTOK * NTOK);
    for (int idx = tid; idx < NTOK * NTOK; idx += 64) {
        int i = idx / NTOK, j = idx - i * NTOK;
        Ps[i * 51 + j] = cp[idx];
    }
    __syncthreads();

    int i = tid;
    if (i < NTOK) {
        // Q row as 16 packed f32x2
        uint64_t q2r[16];
        const uint64_t* qrow = reinterpret_cast<const uint64_t*>(Os + i * 34);
#pragma unroll
        for (int p = 0; p < 16; p++) q2r[p] = qrow[p];

        // pass 1: scores (packed dot, LDS.128) + max
        float mx = -1e30f;
        for (int j = 0; j < NTOK; j++) {
            uint64_t s2 = 0;
            const uint4* kr4 = reinterpret_cast<const uint4*>(Ks + j * 32);
#pragma unroll
            for (int p4 = 0; p4 < 8; p4++) {
                uint4 kv = kr4[p4];
                fma2(s2, q2r[2 * p4],     pack2u(kv.x, kv.y));
                fma2(s2, q2r[2 * p4 + 1], pack2u(kv.z, kv.w));
            }
            float lo, hi; unpack2(s2, lo, hi);
            float s = Ps[i * 51 + j] + lo + hi;
            Ps[i * 51 + j] = s;
            mx = fmaxf(mx, s);
        }

        // pass 2: fused exp + sum + packed PV accumulate (LDS.128)
        float sum = 0.f;
        uint64_t o2[16];
#pragma unroll
        for (int p = 0; p < 16; p++) o2[p] = 0;
        for (int j = 0; j < NTOK; j++) {
            float e = __expf(Ps[i * 51 + j] - mx);
            sum += e;
            uint64_t e2 = pack2(e, e);
            const uint4* vr4 = reinterpret_cast<const uint4*>(Vs + j * 32);
#pragma unroll
            for (int p4 = 0; p4 < 8; p4++) {
                uint4 vv = vr4[p4];
                fma2(o2[2 * p4],     e2, pack2u(vv.x, vv.y));
                fma2(o2[2 * p4 + 1], e2, pack2u(vv.z, vv.w));
            }
        }
        float inv = 1.0f / sum;
#pragma unroll
        for (int p = 0; p < 16; p++) {
            float lo, hi; unpack2(o2[p], lo, hi);
            Os[i * 34 + 2 * p]     = lo * inv;
            Os[i * 34 + 2 * p + 1] = hi * inv;
        }
    }
    __syncthreads();

    bf16* op = g_atth + (size_t)win * (NTOK * CC) + head * HDD;
    for (int idx = tid; idx < NTOK * 16; idx += 64) {
        int i2 = idx >> 4, dp = idx & 15;
        float a = Os[i2 * 34 + dp * 2], b = Os[i2 * 34 + dp * 2 + 1];
        *reinterpret_cast<bf162*>(op + i2 * CC + dp * 2) = __floats2bfloat162_rn(a, b);
    }
}

// ---------------------------------------------------------------------------
// Launch
// ---------------------------------------------------------------------------
extern "C" void kernel_launch(void* const* d_in, const int* in_sizes, int n_in,
                              void* d_out, int out_size) {
    const float* x         = (const float*)d_in[0];
    const float* attn_mask = (const float*)d_in[1];
    const int*   rel_index = (const int*)  d_in[2];
    const float* n1g       = (const float*)d_in[3];
    const float* n1b       = (const float*)d_in[4];
    const float* qkv_w     = (const float*)d_in[5];
    const float* qkv_b     = (const float*)d_in[6];
    const float* proj_w    = (const float*)d_in[7];
    const float* proj_b    = (const float*)d_in[8];
    const float* tbl       = (const float*)d_in[9];
    const float* n2g       = (const float*)d_in[10];
    const float* n2b       = (const float*)d_in[11];
    const float* fc1_w     = (const float*)d_in[12];
    const float* fc1_b     = (const float*)d_in[13];
    const float* fc2_w     = (const float*)d_in[14];
    const float* fc2_b     = (const float*)d_in[15];
    float* out = (float*)d_out;

    k_prep<<<432, 256>>>(qkv_w, proj_w, fc1_w, fc2_w);
    k_ln1 <<<MTOK / 8, 256>>>(x, n1g, n1b);
    k_comb<<<256 * NHH, 256>>>(attn_mask, rel_index, tbl);
    k_gemm_qkv <<<dim3(3, MTOK / 128), 256>>>(qkv_b);
    k_attn<<<NWIN * NHH, 64>>>();
    k_gemm_proj<<<dim3(1, MTOK / 128), 256>>>(proj_b, x);
    k_mlp<<<MTOK / 64, 256>>>(n2g, n2b, fc1_b, fc2_b, out);
}